// round 1
// baseline (speedup 1.0000x reference)
#include <cuda_runtime.h>
#include <cuda_bf16.h>
#include <math.h>

// Problem constants
#define B_DIM 2
#define S_DIM 2048
#define T_DIM 4096      // B*S tokens
#define H_DIM 1024
#define I_DIM 2048
#define E_DIM 8
#define TOPK 2
#define NPAIR (T_DIM * TOPK)   // 8192

// ---------------------------------------------------------------------------
// Static device scratch (no allocations allowed)
// ---------------------------------------------------------------------------
__device__ float g_scratch_gu[(size_t)NPAIR * 4096];   // 128 MB: [pair, 0:2048]=gate->h, [2048:4096]=up
__device__ float g_partial[(size_t)NPAIR * H_DIM];     // 32 MB: weighted per-pair down-proj output
__device__ int   g_count[E_DIM];
__device__ int   g_cursor[E_DIM];
__device__ int   g_offs[E_DIM + 1];
__device__ int   g_expert_sel[NPAIR];
__device__ float g_pair_w[NPAIR];
__device__ int   g_row_token[NPAIR];
__device__ float g_row_weight[NPAIR];
__device__ int   g_row_of_pair[NPAIR];

// ---------------------------------------------------------------------------
// 0) init: zero counters
// ---------------------------------------------------------------------------
__global__ void init_kernel() {
    int i = threadIdx.x;
    if (i < E_DIM) { g_count[i] = 0; g_cursor[i] = 0; }
}

// ---------------------------------------------------------------------------
// 1) router: logits, softmax top-2, renormalized weights. One warp per token.
// ---------------------------------------------------------------------------
__global__ void router_kernel(const float* __restrict__ x,
                              const float* __restrict__ rw,
                              float* __restrict__ logits_out,
                              int write_logits) {
    int t = blockIdx.x * 8 + (threadIdx.x >> 5);
    if (t >= T_DIM) return;
    int lane = threadIdx.x & 31;
    float acc[E_DIM];
#pragma unroll
    for (int e = 0; e < E_DIM; e++) acc[e] = 0.f;
    const float* xp = x + (size_t)t * H_DIM;
    for (int h = lane; h < H_DIM; h += 32) {
        float xv = xp[h];
        const float* r = rw + (size_t)h * E_DIM;
#pragma unroll
        for (int e = 0; e < E_DIM; e++) acc[e] += xv * r[e];
    }
#pragma unroll
    for (int e = 0; e < E_DIM; e++) {
#pragma unroll
        for (int off = 16; off; off >>= 1)
            acc[e] += __shfl_xor_sync(0xffffffffu, acc[e], off);
    }
    if (lane == 0) {
        if (write_logits) {
#pragma unroll
            for (int e = 0; e < E_DIM; e++) logits_out[(size_t)t * E_DIM + e] = acc[e];
        }
        // top-2 over logits (== top-2 over softmax probs); lower index wins ties
        int e0 = 0;
#pragma unroll
        for (int e = 1; e < E_DIM; e++) if (acc[e] > acc[e0]) e0 = e;
        int e1 = (e0 == 0) ? 1 : 0;
#pragma unroll
        for (int e = 0; e < E_DIM; e++)
            if (e != e0 && acc[e] > acc[e1]) e1 = e;
        float l0 = acc[e0], l1 = acc[e1];
        float r1 = expf(l1 - l0);        // <= 1
        float s  = 1.0f + r1;
        float w0 = 1.0f / s;
        float w1 = r1 / s;
        g_expert_sel[t * 2 + 0] = e0;
        g_expert_sel[t * 2 + 1] = e1;
        g_pair_w[t * 2 + 0] = w0;
        g_pair_w[t * 2 + 1] = w1;
        atomicAdd(&g_count[e0], 1);
        atomicAdd(&g_count[e1], 1);
    }
}

// ---------------------------------------------------------------------------
// 2) exclusive prefix over counts
// ---------------------------------------------------------------------------
__global__ void offsets_kernel() {
    if (threadIdx.x == 0) {
        int acc = 0;
        g_offs[0] = 0;
#pragma unroll
        for (int e = 0; e < E_DIM; e++) { acc += g_count[e]; g_offs[e + 1] = acc; }
    }
}

// ---------------------------------------------------------------------------
// 3) scatter pairs to expert-sorted rows
// ---------------------------------------------------------------------------
__global__ void scatter_kernel() {
    int p = blockIdx.x * 256 + threadIdx.x;
    if (p >= NPAIR) return;
    int e = g_expert_sel[p];
    int r = g_offs[e] + atomicAdd(&g_cursor[e], 1);
    g_row_token[r]  = p >> 1;
    g_row_weight[r] = g_pair_w[p];
    g_row_of_pair[p] = r;
}

// ---------------------------------------------------------------------------
// 4) GEMM1: [rows_e, 4096] = Xgather[rows_e, 1024] @ [gate_w | up_w][1024, 4096]
//    128x128x8 tiles, 8x8 per-thread, 256 threads.
// ---------------------------------------------------------------------------
#define BM 128
#define BN 128
#define BK 8

__global__ void __launch_bounds__(256) moe_gemm1(
    const float* __restrict__ x,
    const float* __restrict__ gate_w,
    const float* __restrict__ up_w) {
    int e = blockIdx.z;
    int rowBeg = g_offs[e] + blockIdx.y * BM;
    int rowEnd = g_offs[e + 1];
    if (rowBeg >= rowEnd) return;
    int nBase = blockIdx.x * BN;   // 0..4095
    const float* Bp = (nBase < I_DIM)
        ? (gate_w + (size_t)e * H_DIM * I_DIM + nBase)
        : (up_w   + (size_t)e * H_DIM * I_DIM + (nBase - I_DIM));

    __shared__ float As[BK][BM];
    __shared__ float Bs[BK][BN];

    int tid = threadIdx.x;
    int tx = tid & 15, ty = tid >> 4;
    float acc[8][8];
#pragma unroll
    for (int i = 0; i < 8; i++)
#pragma unroll
        for (int j = 0; j < 8; j++) acc[i][j] = 0.f;

    int arow = tid >> 1;          // 0..127
    int ak4  = (tid & 1) * 4;     // 0 or 4
    int grow = rowBeg + arow;
    const float* aptr = nullptr;
    if (grow < rowEnd) aptr = x + (size_t)g_row_token[grow] * H_DIM;
    int brow = tid >> 5;          // 0..7
    int bn4  = (tid & 31) * 4;

    for (int k0 = 0; k0 < H_DIM; k0 += BK) {
        float4 av = aptr ? *(const float4*)(aptr + k0 + ak4)
                         : make_float4(0.f, 0.f, 0.f, 0.f);
        As[ak4 + 0][arow] = av.x; As[ak4 + 1][arow] = av.y;
        As[ak4 + 2][arow] = av.z; As[ak4 + 3][arow] = av.w;
        *(float4*)&Bs[brow][bn4] =
            *(const float4*)(Bp + (size_t)(k0 + brow) * I_DIM + bn4);
        __syncthreads();
#pragma unroll
        for (int k = 0; k < BK; k++) {
            float ar[8], br[8];
#pragma unroll
            for (int i = 0; i < 8; i++) ar[i] = As[k][ty * 8 + i];
#pragma unroll
            for (int j = 0; j < 8; j++) br[j] = Bs[k][tx * 8 + j];
#pragma unroll
            for (int i = 0; i < 8; i++)
#pragma unroll
                for (int j = 0; j < 8; j++) acc[i][j] += ar[i] * br[j];
        }
        __syncthreads();
    }
#pragma unroll
    for (int i = 0; i < 8; i++) {
        int r = rowBeg + ty * 8 + i;
        if (r < rowEnd) {
            float* cp = g_scratch_gu + (size_t)r * 4096 + nBase + tx * 8;
#pragma unroll
            for (int j = 0; j < 8; j += 4)
                *(float4*)(cp + j) = make_float4(acc[i][j], acc[i][j + 1],
                                                 acc[i][j + 2], acc[i][j + 3]);
        }
    }
}

// ---------------------------------------------------------------------------
// 5) h = silu(gate) * up, in place over the gate half
// ---------------------------------------------------------------------------
__global__ void silu_kernel() {
    int idx = blockIdx.x * 256 + threadIdx.x;   // over NPAIR*2048/4 float4
    if (idx >= NPAIR * (I_DIM / 4)) return;
    int p = idx / (I_DIM / 4);
    int j = (idx % (I_DIM / 4)) * 4;
    float* base = g_scratch_gu + (size_t)p * 4096;
    float4 g = *(float4*)(base + j);
    float4 u = *(float4*)(base + I_DIM + j);
    float4 h;
    h.x = (g.x / (1.0f + expf(-g.x))) * u.x;
    h.y = (g.y / (1.0f + expf(-g.y))) * u.y;
    h.z = (g.z / (1.0f + expf(-g.z))) * u.z;
    h.w = (g.w / (1.0f + expf(-g.w))) * u.w;
    *(float4*)(base + j) = h;
}

// ---------------------------------------------------------------------------
// 6) GEMM2: partial[rows_e, 1024] = h[rows_e, 2048] @ out_w[e][2048,1024],
//    scaled by per-row routing weight.
// ---------------------------------------------------------------------------
__global__ void __launch_bounds__(256) moe_gemm2(const float* __restrict__ out_w) {
    int e = blockIdx.z;
    int rowBeg = g_offs[e] + blockIdx.y * BM;
    int rowEnd = g_offs[e + 1];
    if (rowBeg >= rowEnd) return;
    int nBase = blockIdx.x * BN;   // 0..1023
    const float* Bp = out_w + (size_t)e * I_DIM * H_DIM + nBase;

    __shared__ float As[BK][BM];
    __shared__ float Bs[BK][BN];

    int tid = threadIdx.x;
    int tx = tid & 15, ty = tid >> 4;
    float acc[8][8];
#pragma unroll
    for (int i = 0; i < 8; i++)
#pragma unroll
        for (int j = 0; j < 8; j++) acc[i][j] = 0.f;

    int arow = tid >> 1;
    int ak4  = (tid & 1) * 4;
    int grow = rowBeg + arow;
    const float* aptr = (grow < rowEnd)
        ? (g_scratch_gu + (size_t)grow * 4096) : nullptr;
    int brow = tid >> 5;
    int bn4  = (tid & 31) * 4;

    for (int k0 = 0; k0 < I_DIM; k0 += BK) {
        float4 av = aptr ? *(const float4*)(aptr + k0 + ak4)
                         : make_float4(0.f, 0.f, 0.f, 0.f);
        As[ak4 + 0][arow] = av.x; As[ak4 + 1][arow] = av.y;
        As[ak4 + 2][arow] = av.z; As[ak4 + 3][arow] = av.w;
        *(float4*)&Bs[brow][bn4] =
            *(const float4*)(Bp + (size_t)(k0 + brow) * H_DIM + bn4);
        __syncthreads();
#pragma unroll
        for (int k = 0; k < BK; k++) {
            float ar[8], br[8];
#pragma unroll
            for (int i = 0; i < 8; i++) ar[i] = As[k][ty * 8 + i];
#pragma unroll
            for (int j = 0; j < 8; j++) br[j] = Bs[k][tx * 8 + j];
#pragma unroll
            for (int i = 0; i < 8; i++)
#pragma unroll
                for (int j = 0; j < 8; j++) acc[i][j] += ar[i] * br[j];
        }
        __syncthreads();
    }
#pragma unroll
    for (int i = 0; i < 8; i++) {
        int r = rowBeg + ty * 8 + i;
        if (r < rowEnd) {
            float w = g_row_weight[r];
            float* cp = g_partial + (size_t)r * H_DIM + nBase + tx * 8;
#pragma unroll
            for (int j = 0; j < 8; j += 4)
                *(float4*)(cp + j) = make_float4(w * acc[i][j], w * acc[i][j + 1],
                                                 w * acc[i][j + 2], w * acc[i][j + 3]);
        }
    }
}

// ---------------------------------------------------------------------------
// 7) combine: out[t] = partial[row_of(t,0)] + partial[row_of(t,1)]
// ---------------------------------------------------------------------------
__global__ void combine_kernel(float* __restrict__ out) {
    int idx = blockIdx.x * 256 + threadIdx.x;   // T * H/4 float4
    if (idx >= T_DIM * (H_DIM / 4)) return;
    int t = idx >> 8;                // H/4 = 256
    int j = (idx & 255) * 4;
    int r0 = g_row_of_pair[2 * t];
    int r1 = g_row_of_pair[2 * t + 1];
    float4 a = *(float4*)&g_partial[(size_t)r0 * H_DIM + j];
    float4 b = *(float4*)&g_partial[(size_t)r1 * H_DIM + j];
    float4 o;
    o.x = a.x + b.x; o.y = a.y + b.y; o.z = a.z + b.z; o.w = a.w + b.w;
    *(float4*)(out + (size_t)t * H_DIM + j) = o;
}

// ---------------------------------------------------------------------------
// launch
// ---------------------------------------------------------------------------
extern "C" void kernel_launch(void* const* d_in, const int* in_sizes, int n_in,
                              void* d_out, int out_size) {
    const float* x  = (const float*)d_in[0];   // [B,S,H]
    const float* rw = (const float*)d_in[1];   // [H,E]
    const float* gw = (const float*)d_in[2];   // [E,H,I]
    const float* uw = (const float*)d_in[3];   // [E,H,I]
    const float* ow = (const float*)d_in[4];   // [E,I,H]
    float* out = (float*)d_out;

    // output layout: [T*H] main output, then (if room) [T*E] router logits
    int write_logits = (out_size >= T_DIM * H_DIM + T_DIM * E_DIM) ? 1 : 0;
    float* logits = out + (size_t)T_DIM * H_DIM;

    init_kernel<<<1, 32>>>();
    router_kernel<<<T_DIM / 8, 256>>>(x, rw, logits, write_logits);
    offsets_kernel<<<1, 32>>>();
    scatter_kernel<<<NPAIR / 256, 256>>>();

    // GEMM1: N=4096 -> 32 n-tiles; up to 4096 rows/expert -> 32 m-tiles
    moe_gemm1<<<dim3(32, 32, E_DIM), 256>>>(x, gw, uw);
    silu_kernel<<<(NPAIR * (I_DIM / 4) + 255) / 256, 256>>>();
    // GEMM2: N=1024 -> 8 n-tiles
    moe_gemm2<<<dim3(8, 32, E_DIM), 256>>>(ow);
    combine_kernel<<<(T_DIM * (H_DIM / 4) + 255) / 256, 256>>>(out);
}

// round 12
// speedup vs baseline: 1.7648x; 1.7648x over previous
#include <cuda_runtime.h>
#include <cuda_bf16.h>
#include <cstdint>
#include <math.h>

// Problem constants
#define T_DIM 4096
#define H_DIM 1024
#define I_DIM 2048
#define E_DIM 8
#define NPAIR (T_DIM * 2)   // 8192

// ---------------------------------------------------------------------------
// Static device scratch (no allocations allowed).
// NOTE: these symbols are ONLY referenced from device code (passing them as
// kernel arguments from host code was the R7-R11 zero-output bug).
// ---------------------------------------------------------------------------
__device__ __nv_bfloat16 g_B1h[(size_t)E_DIM * 4096 * H_DIM];   // interleaved: row 2i=gate_i, 2i+1=up_i; K-major
__device__ __nv_bfloat16 g_B1l[(size_t)E_DIM * 4096 * H_DIM];
__device__ __nv_bfloat16 g_W2h[(size_t)E_DIM * H_DIM * I_DIM];  // [e][n=1024][k=2048]
__device__ __nv_bfloat16 g_W2l[(size_t)E_DIM * H_DIM * I_DIM];
__device__ __nv_bfloat16 g_A1h[(size_t)NPAIR * H_DIM];
__device__ __nv_bfloat16 g_A1l[(size_t)NPAIR * H_DIM];
__device__ __nv_bfloat16 g_Hh[(size_t)NPAIR * I_DIM];
__device__ __nv_bfloat16 g_Hl[(size_t)NPAIR * I_DIM];
__device__ float g_partial[(size_t)NPAIR * H_DIM];
__device__ int   g_count[E_DIM];
__device__ int   g_cursor[E_DIM];
__device__ int   g_offs[E_DIM + 1];
__device__ int   g_expert_sel[NPAIR];
__device__ float g_pair_w[NPAIR];
__device__ int   g_row_token[NPAIR];
__device__ float g_row_weight[NPAIR];
__device__ int   g_row_of_pair[NPAIR];

// ---------------------------------------------------------------------------
// MMA: m16n8k16 row.col f32.bf16.bf16.f32 (plain, no ldmatrix anywhere)
// ---------------------------------------------------------------------------
#define MMA16816(d, a, b0, b1) \
    asm volatile("mma.sync.aligned.m16n8k16.row.col.f32.bf16.bf16.f32 " \
                 "{%0,%1,%2,%3}, {%4,%5,%6,%7}, {%8,%9}, {%0,%1,%2,%3};" \
                 : "+f"((d)[0]), "+f"((d)[1]), "+f"((d)[2]), "+f"((d)[3]) \
                 : "r"((a)[0]), "r"((a)[1]), "r"((a)[2]), "r"((a)[3]), "r"(b0), "r"(b1))

// ---------------------------------------------------------------------------
// 0) init
// ---------------------------------------------------------------------------
__global__ void init_kernel() {
    int i = threadIdx.x;
    if (i < E_DIM) { g_count[i] = 0; g_cursor[i] = 0; }
}

// ---------------------------------------------------------------------------
// 1) router
// ---------------------------------------------------------------------------
__global__ void router_kernel(const float* __restrict__ x,
                              const float* __restrict__ rw,
                              float* __restrict__ logits_out,
                              int write_logits) {
    int t = blockIdx.x * 8 + (threadIdx.x >> 5);
    if (t >= T_DIM) return;
    int lane = threadIdx.x & 31;
    float acc[E_DIM];
#pragma unroll
    for (int e = 0; e < E_DIM; e++) acc[e] = 0.f;
    const float* xp = x + (size_t)t * H_DIM;
    for (int h = lane; h < H_DIM; h += 32) {
        float xv = xp[h];
        const float* r = rw + (size_t)h * E_DIM;
#pragma unroll
        for (int e = 0; e < E_DIM; e++) acc[e] += xv * r[e];
    }
#pragma unroll
    for (int e = 0; e < E_DIM; e++) {
#pragma unroll
        for (int off = 16; off; off >>= 1)
            acc[e] += __shfl_xor_sync(0xffffffffu, acc[e], off);
    }
    if (lane == 0) {
        if (write_logits) {
#pragma unroll
            for (int e = 0; e < E_DIM; e++) logits_out[(size_t)t * E_DIM + e] = acc[e];
        }
        int e0 = 0;
#pragma unroll
        for (int e = 1; e < E_DIM; e++) if (acc[e] > acc[e0]) e0 = e;
        int e1 = (e0 == 0) ? 1 : 0;
#pragma unroll
        for (int e = 0; e < E_DIM; e++)
            if (e != e0 && acc[e] > acc[e1]) e1 = e;
        float r1 = expf(acc[e1] - acc[e0]);
        float s  = 1.0f + r1;
        g_expert_sel[t * 2 + 0] = e0;
        g_expert_sel[t * 2 + 1] = e1;
        g_pair_w[t * 2 + 0] = 1.0f / s;
        g_pair_w[t * 2 + 1] = r1 / s;
        atomicAdd(&g_count[e0], 1);
        atomicAdd(&g_count[e1], 1);
    }
}

// ---------------------------------------------------------------------------
// 2) offsets  3) scatter
// ---------------------------------------------------------------------------
__global__ void offsets_kernel() {
    if (threadIdx.x == 0) {
        int acc = 0;
        g_offs[0] = 0;
#pragma unroll
        for (int e = 0; e < E_DIM; e++) { acc += g_count[e]; g_offs[e + 1] = acc; }
    }
}

__global__ void scatter_kernel() {
    int p = blockIdx.x * 256 + threadIdx.x;
    if (p >= NPAIR) return;
    int e = g_expert_sel[p];
    int r = g_offs[e] + atomicAdd(&g_cursor[e], 1);
    g_row_token[r]  = p >> 1;
    g_row_weight[r] = g_pair_w[p];
    g_row_of_pair[p] = r;
}

// ---------------------------------------------------------------------------
// 4) weight conversion: fp32 [e][K][N] (N contiguous) -> bf16 hi/lo K-major,
//    dst row = n*rowMul + rowAdd. dstSel picks the device-global destination
//    INSIDE device code (0: g_B1h/g_B1l, 1: g_W2h/g_W2l).
// ---------------------------------------------------------------------------
__global__ void conv_transpose_kernel(const float* __restrict__ src,
                                      int dstSel,
                                      int K, int N, int dstERows,
                                      int rowMul, int rowAdd) {
    __nv_bfloat16* dh = (dstSel == 0) ? g_B1h : g_W2h;
    __nv_bfloat16* dl = (dstSel == 0) ? g_B1l : g_W2l;
    __shared__ float tile[32][33];
    int e = blockIdx.z;
    int k0 = blockIdx.y * 32, n0 = blockIdx.x * 32;
    const float* s = src + (size_t)e * K * N;
    int tx = threadIdx.x, ty = threadIdx.y;   // 32 x 8
#pragma unroll
    for (int i = 0; i < 32; i += 8)
        tile[ty + i][tx] = s[(size_t)(k0 + ty + i) * N + n0 + tx];
    __syncthreads();
#pragma unroll
    for (int i = 0; i < 32; i += 8) {
        float v = tile[tx][ty + i];
        __nv_bfloat16 hi = __float2bfloat16(v);
        __nv_bfloat16 lo = __float2bfloat16(v - __bfloat162float(hi));
        size_t row = (size_t)e * dstERows + (size_t)(n0 + ty + i) * rowMul + rowAdd;
        dh[row * K + k0 + tx] = hi;
        dl[row * K + k0 + tx] = lo;
    }
}

// ---------------------------------------------------------------------------
// 5) gather + split activations
// ---------------------------------------------------------------------------
__global__ void convA_kernel(const float* __restrict__ x) {
    int r = blockIdx.x;
    int c = threadIdx.x * 4;
    int token = g_row_token[r];
    float4 v = *(const float4*)(x + (size_t)token * H_DIM + c);
    size_t base = (size_t)r * H_DIM + c;
    float vv[4] = {v.x, v.y, v.z, v.w};
#pragma unroll
    for (int i = 0; i < 4; i++) {
        __nv_bfloat16 hi = __float2bfloat16(vv[i]);
        g_A1h[base + i] = hi;
        g_A1l[base + i] = __float2bfloat16(vv[i] - __bfloat162float(hi));
    }
}

// ---------------------------------------------------------------------------
// 6/7) Plain-smem HMMA grouped GEMM: D[128x128] = A[128xK] @ B[128xK]^T,
//   split bf16 (3 products). NO cp.async, NO ldmatrix. All operand arrays
//   resolved from device globals via the SRC tag (NO device symbols passed
//   from host). SRC=0: A=g_A1h/l, B=g_B1h/l (FUSE epilogue -> g_Hh/l).
//   SRC=1: A=g_Hh/l, B=g_W2h/l (weighted epilogue -> g_partial).
// ---------------------------------------------------------------------------
#define ROW_P 80                  // bytes per row (64B data + 16B pad)
#define TILE_B (128 * ROW_P)      // 10240
#define SMEM_SZ (4 * TILE_B)      // 40960 < 48KB default

template <int KHALVES, int ASTR, int BSTR, int BEROWS, bool FUSE, int SRC>
__global__ void __launch_bounds__(256, 1) mma_gemm() {
    const __nv_bfloat16* __restrict__ Ah = (SRC == 0) ? g_A1h : g_Hh;
    const __nv_bfloat16* __restrict__ Al = (SRC == 0) ? g_A1l : g_Hl;
    const __nv_bfloat16* __restrict__ Bh = (SRC == 0) ? g_B1h : g_W2h;
    const __nv_bfloat16* __restrict__ Bl = (SRC == 0) ? g_B1l : g_W2l;

    extern __shared__ char smem[];
    int e = blockIdx.z;
    int rowBeg = g_offs[e] + blockIdx.y * 128;
    int rowEnd = g_offs[e + 1];
    if (rowBeg >= rowEnd) return;
    int bx = blockIdx.x;
    int bRowBase = e * BEROWS + bx * 128;

    const int tid = threadIdx.x;
    const int wid = tid >> 5, lane = tid & 31;
    const int wm = wid >> 2, wn = wid & 3;

    // ---- per-thread staging descriptors: 8 x 16B per k-chunk of 32 halves ----
    const __nv_bfloat16* gptr[8];
    uint32_t sOff[8];
    bool     gok[8];
#pragma unroll
    for (int j = 0; j < 8; j++) {
        int id  = j * 256 + tid;
        int arr = id >> 9;              // 0:Ah 1:Al 2:Bh 3:Bl
        int q   = id & 511;
        int row = q >> 2;
        int c16 = q & 3;
        sOff[j] = arr * TILE_B + row * ROW_P + c16 * 16;
        if (arr < 2) {
            int grow = rowBeg + row;
            bool ok = grow < rowEnd;
            int cr = ok ? grow : rowBeg;
            const __nv_bfloat16* p = (arr == 0) ? Ah : Al;
            gptr[j] = p + (size_t)cr * ASTR + c16 * 8;
            gok[j] = ok;
        } else {
            const __nv_bfloat16* p = (arr == 2) ? Bh : Bl;
            gptr[j] = p + (size_t)(bRowBase + row) * BSTR + c16 * 8;
            gok[j] = true;
        }
    }

    float d[4][4][4];
#pragma unroll
    for (int i = 0; i < 4; i++)
#pragma unroll
        for (int j = 0; j < 4; j++)
#pragma unroll
            for (int c = 0; c < 4; c++) d[i][j][c] = 0.f;

    // fragment shared-word offsets, per documented m16n8k16 fragment layout
    const int fr = lane >> 2;          // row/col within 8
    const int fkB = (lane & 3) * 4;    // k pair -> bytes (2 halves)

    for (int k0 = 0; k0 < KHALVES; k0 += 32) {
        // stage tiles
#pragma unroll
        for (int j = 0; j < 8; j++) {
            uint4 v = gok[j] ? *(const uint4*)(gptr[j] + k0) : make_uint4(0, 0, 0, 0);
            *(uint4*)(smem + sOff[j]) = v;
        }
        __syncthreads();

#pragma unroll
        for (int ks = 0; ks < 2; ks++) {
            const int kB = ks * 32 + fkB;
            uint32_t bh[4][2], bl[4][2];
#pragma unroll
            for (int n8 = 0; n8 < 4; n8++) {
                int nOff = (wn * 32 + n8 * 8 + fr) * ROW_P + kB;
                bh[n8][0] = *(const uint32_t*)(smem + 2 * TILE_B + nOff);
                bh[n8][1] = *(const uint32_t*)(smem + 2 * TILE_B + nOff + 16);
                bl[n8][0] = *(const uint32_t*)(smem + 3 * TILE_B + nOff);
                bl[n8][1] = *(const uint32_t*)(smem + 3 * TILE_B + nOff + 16);
            }
#pragma unroll
            for (int mt = 0; mt < 4; mt++) {
                int mOff = (wm * 64 + mt * 16 + fr) * ROW_P + kB;
                uint32_t ah[4], al[4];
                ah[0] = *(const uint32_t*)(smem + 0 * TILE_B + mOff);
                ah[1] = *(const uint32_t*)(smem + 0 * TILE_B + mOff + 8 * ROW_P);
                ah[2] = *(const uint32_t*)(smem + 0 * TILE_B + mOff + 16);
                ah[3] = *(const uint32_t*)(smem + 0 * TILE_B + mOff + 8 * ROW_P + 16);
                al[0] = *(const uint32_t*)(smem + 1 * TILE_B + mOff);
                al[1] = *(const uint32_t*)(smem + 1 * TILE_B + mOff + 8 * ROW_P);
                al[2] = *(const uint32_t*)(smem + 1 * TILE_B + mOff + 16);
                al[3] = *(const uint32_t*)(smem + 1 * TILE_B + mOff + 8 * ROW_P + 16);
#pragma unroll
                for (int n8 = 0; n8 < 4; n8++) {
                    MMA16816(d[mt][n8], ah, bh[n8][0], bh[n8][1]);
                    MMA16816(d[mt][n8], ah, bl[n8][0], bl[n8][1]);
                    MMA16816(d[mt][n8], al, bh[n8][0], bh[n8][1]);
                }
            }
        }
        __syncthreads();
    }

    // ---- epilogue ----
    // D fragment: c0,c1 at (row=lane/4, col=2*(lane%4)+{0,1}); c2,c3 at row+8.
    if (FUSE) {
        // interleaved B: even col=gate_i, odd col=up_i; i = wn*16 + n8*4 + (lane%4)
        __nv_bfloat16* shh = (__nv_bfloat16*)smem;           // [128][72] halves
        __nv_bfloat16* shl = shh + 128 * 72;
        int g4 = lane >> 2, t4 = lane & 3;
#pragma unroll
        for (int mt = 0; mt < 4; mt++) {
#pragma unroll
            for (int n8 = 0; n8 < 4; n8++) {
                int r0 = wm * 64 + mt * 16 + g4;
                int i0 = wn * 16 + n8 * 4 + t4;
                float g0 = d[mt][n8][0], u0 = d[mt][n8][1];
                float h0 = (g0 / (1.0f + expf(-g0))) * u0;
                __nv_bfloat16 hh0 = __float2bfloat16(h0);
                shh[r0 * 72 + i0] = hh0;
                shl[r0 * 72 + i0] = __float2bfloat16(h0 - __bfloat162float(hh0));
                float g1 = d[mt][n8][2], u1 = d[mt][n8][3];
                float h1 = (g1 / (1.0f + expf(-g1))) * u1;
                __nv_bfloat16 hh1 = __float2bfloat16(h1);
                shh[(r0 + 8) * 72 + i0] = hh1;
                shl[(r0 + 8) * 72 + i0] = __float2bfloat16(h1 - __bfloat162float(hh1));
            }
        }
        __syncthreads();
        int iBase = bx * 64;
#pragma unroll
        for (int j = 0; j < 8; j++) {
            int id = j * 256 + tid;          // 0..2047
            int arrSel = id >> 10;
            int q = id & 1023;
            int row = q >> 3;
            int cc = q & 7;
            int grow = rowBeg + row;
            if (grow < rowEnd) {
                const char* s = smem + (size_t)arrSel * (128 * 72 * 2) + row * 144 + cc * 16;
                __nv_bfloat16* dptr = (arrSel ? g_Hl : g_Hh) + (size_t)grow * I_DIM + iBase + cc * 8;
                *(uint4*)dptr = *(const uint4*)s;
            }
        }
    } else {
        int g4 = lane >> 2, t4 = lane & 3;
#pragma unroll
        for (int mt = 0; mt < 4; mt++) {
#pragma unroll
            for (int n8 = 0; n8 < 4; n8++) {
                int r0 = rowBeg + wm * 64 + mt * 16 + g4;
                int col = bx * 128 + wn * 32 + n8 * 8 + t4 * 2;
                if (r0 < rowEnd) {
                    float w = g_row_weight[r0];
                    float2 v = make_float2(w * d[mt][n8][0], w * d[mt][n8][1]);
                    *(float2*)&g_partial[(size_t)r0 * H_DIM + col] = v;
                }
                int r1 = r0 + 8;
                if (r1 < rowEnd) {
                    float w = g_row_weight[r1];
                    float2 v = make_float2(w * d[mt][n8][2], w * d[mt][n8][3]);
                    *(float2*)&g_partial[(size_t)r1 * H_DIM + col] = v;
                }
            }
        }
    }
}

// ---------------------------------------------------------------------------
// 8) combine
// ---------------------------------------------------------------------------
__global__ void combine_kernel(float* __restrict__ out) {
    int idx = blockIdx.x * 256 + threadIdx.x;
    if (idx >= T_DIM * (H_DIM / 4)) return;
    int t = idx >> 8;
    int j = (idx & 255) * 4;
    int r0 = g_row_of_pair[2 * t];
    int r1 = g_row_of_pair[2 * t + 1];
    float4 a = *(float4*)&g_partial[(size_t)r0 * H_DIM + j];
    float4 b = *(float4*)&g_partial[(size_t)r1 * H_DIM + j];
    float4 o;
    o.x = a.x + b.x; o.y = a.y + b.y; o.z = a.z + b.z; o.w = a.w + b.w;
    *(float4*)(out + (size_t)t * H_DIM + j) = o;
}

// ---------------------------------------------------------------------------
// launch
// ---------------------------------------------------------------------------
extern "C" void kernel_launch(void* const* d_in, const int* in_sizes, int n_in,
                              void* d_out, int out_size) {
    const float* x  = (const float*)d_in[0];
    const float* rw = (const float*)d_in[1];
    const float* gw = (const float*)d_in[2];
    const float* uw = (const float*)d_in[3];
    const float* ow = (const float*)d_in[4];
    float* out = (float*)d_out;

    int write_logits = (out_size >= T_DIM * H_DIM + T_DIM * E_DIM) ? 1 : 0;
    float* logits = out + (size_t)T_DIM * H_DIM;

    init_kernel<<<1, 32>>>();
    router_kernel<<<T_DIM / 8, 256>>>(x, rw, logits, write_logits);
    offsets_kernel<<<1, 32>>>();
    scatter_kernel<<<NPAIR / 256, 256>>>();

    // weight conversion (transpose + hi/lo split); gate/up interleaved
    dim3 cb(32, 8);
    conv_transpose_kernel<<<dim3(I_DIM / 32, H_DIM / 32, E_DIM), cb>>>(gw, 0, H_DIM, I_DIM, 4096, 2, 0);
    conv_transpose_kernel<<<dim3(I_DIM / 32, H_DIM / 32, E_DIM), cb>>>(uw, 0, H_DIM, I_DIM, 4096, 2, 1);
    conv_transpose_kernel<<<dim3(H_DIM / 32, I_DIM / 32, E_DIM), cb>>>(ow, 1, I_DIM, H_DIM, 1024, 1, 0);
    convA_kernel<<<NPAIR, 256>>>(x);

    // plain-smem HMMA grouped GEMMs (40KB dynamic smem, no attribute needed)
    mma_gemm<1024, 1024, 1024, 4096, true, 0><<<dim3(32, 32, E_DIM), 256, SMEM_SZ>>>();
    mma_gemm<2048, 2048, 2048, 1024, false, 1><<<dim3(8, 32, E_DIM), 256, SMEM_SZ>>>();

    combine_kernel<<<(T_DIM * (H_DIM / 4) + 255) / 256, 256>>>(out);
}

// round 13
// speedup vs baseline: 2.2197x; 1.2578x over previous
#include <cuda_runtime.h>
#include <cuda_bf16.h>
#include <cstdint>
#include <math.h>

// Problem constants
#define T_DIM 4096
#define H_DIM 1024
#define I_DIM 2048
#define E_DIM 8
#define NPAIR (T_DIM * 2)   // 8192

// ---------------------------------------------------------------------------
// Static device scratch (no allocations allowed).
// NOTE: referenced ONLY from device code (host-passing these was the R7-R11 bug).
// ---------------------------------------------------------------------------
__device__ __nv_bfloat16 g_B1h[(size_t)E_DIM * 4096 * H_DIM];   // interleaved: row 2i=gate_i, 2i+1=up_i; K-major
__device__ __nv_bfloat16 g_B1l[(size_t)E_DIM * 4096 * H_DIM];
__device__ __nv_bfloat16 g_W2h[(size_t)E_DIM * H_DIM * I_DIM];  // [e][n=1024][k=2048]
__device__ __nv_bfloat16 g_W2l[(size_t)E_DIM * H_DIM * I_DIM];
__device__ __nv_bfloat16 g_A1h[(size_t)NPAIR * H_DIM];
__device__ __nv_bfloat16 g_A1l[(size_t)NPAIR * H_DIM];
__device__ __nv_bfloat16 g_Hh[(size_t)NPAIR * I_DIM];
__device__ __nv_bfloat16 g_Hl[(size_t)NPAIR * I_DIM];
__device__ float g_partial[(size_t)NPAIR * H_DIM];
__device__ int   g_count[E_DIM];
__device__ int   g_cursor[E_DIM];
__device__ int   g_offs[E_DIM + 1];
__device__ int   g_expert_sel[NPAIR];
__device__ float g_pair_w[NPAIR];
__device__ int   g_row_token[NPAIR];
__device__ float g_row_weight[NPAIR];
__device__ int   g_row_of_pair[NPAIR];

// ---------------------------------------------------------------------------
// PTX helpers (arch-portable: cp.async / ldmatrix / mma.sync)
// ---------------------------------------------------------------------------
__device__ __forceinline__ uint32_t smem_to_u32(const void* p) {
    uint32_t a;
    asm("{ .reg .u64 t; cvta.to.shared.u64 t, %1; cvt.u32.u64 %0, t; }" : "=r"(a) : "l"(p));
    return a;
}
__device__ __forceinline__ void cp_async16(uint32_t dst, const void* src, uint32_t srcBytes) {
    asm volatile("cp.async.cg.shared.global [%0], [%1], 16, %2;"
                 :: "r"(dst), "l"(src), "r"(srcBytes) : "memory");
}
__device__ __forceinline__ void cp_commit() {
    asm volatile("cp.async.commit_group;" ::: "memory");
}
template <int N>
__device__ __forceinline__ void cp_wait() {
    asm volatile("cp.async.wait_group %0;" :: "n"(N) : "memory");
}

#define LDSM4(r, addr) \
    asm volatile("ldmatrix.sync.aligned.m8n8.x4.shared.b16 {%0,%1,%2,%3}, [%4];" \
                 : "=r"((r)[0]), "=r"((r)[1]), "=r"((r)[2]), "=r"((r)[3]) : "r"(addr))

#define MMA16816(d, a, b0, b1) \
    asm volatile("mma.sync.aligned.m16n8k16.row.col.f32.bf16.bf16.f32 " \
                 "{%0,%1,%2,%3}, {%4,%5,%6,%7}, {%8,%9}, {%0,%1,%2,%3};" \
                 : "+f"((d)[0]), "+f"((d)[1]), "+f"((d)[2]), "+f"((d)[3]) \
                 : "r"((a)[0]), "r"((a)[1]), "r"((a)[2]), "r"((a)[3]), "r"(b0), "r"(b1))

// ---------------------------------------------------------------------------
// 0) init
// ---------------------------------------------------------------------------
__global__ void init_kernel() {
    int i = threadIdx.x;
    if (i < E_DIM) { g_count[i] = 0; g_cursor[i] = 0; }
}

// ---------------------------------------------------------------------------
// 1) router
// ---------------------------------------------------------------------------
__global__ void router_kernel(const float* __restrict__ x,
                              const float* __restrict__ rw,
                              float* __restrict__ logits_out,
                              int write_logits) {
    int t = blockIdx.x * 8 + (threadIdx.x >> 5);
    if (t >= T_DIM) return;
    int lane = threadIdx.x & 31;
    float acc[E_DIM];
#pragma unroll
    for (int e = 0; e < E_DIM; e++) acc[e] = 0.f;
    const float* xp = x + (size_t)t * H_DIM;
    for (int h = lane; h < H_DIM; h += 32) {
        float xv = xp[h];
        const float* r = rw + (size_t)h * E_DIM;
#pragma unroll
        for (int e = 0; e < E_DIM; e++) acc[e] += xv * r[e];
    }
#pragma unroll
    for (int e = 0; e < E_DIM; e++) {
#pragma unroll
        for (int off = 16; off; off >>= 1)
            acc[e] += __shfl_xor_sync(0xffffffffu, acc[e], off);
    }
    if (lane == 0) {
        if (write_logits) {
#pragma unroll
            for (int e = 0; e < E_DIM; e++) logits_out[(size_t)t * E_DIM + e] = acc[e];
        }
        int e0 = 0;
#pragma unroll
        for (int e = 1; e < E_DIM; e++) if (acc[e] > acc[e0]) e0 = e;
        int e1 = (e0 == 0) ? 1 : 0;
#pragma unroll
        for (int e = 0; e < E_DIM; e++)
            if (e != e0 && acc[e] > acc[e1]) e1 = e;
        float r1 = expf(acc[e1] - acc[e0]);
        float s  = 1.0f + r1;
        g_expert_sel[t * 2 + 0] = e0;
        g_expert_sel[t * 2 + 1] = e1;
        g_pair_w[t * 2 + 0] = 1.0f / s;
        g_pair_w[t * 2 + 1] = r1 / s;
        atomicAdd(&g_count[e0], 1);
        atomicAdd(&g_count[e1], 1);
    }
}

// ---------------------------------------------------------------------------
// 2) offsets  3) scatter
// ---------------------------------------------------------------------------
__global__ void offsets_kernel() {
    if (threadIdx.x == 0) {
        int acc = 0;
        g_offs[0] = 0;
#pragma unroll
        for (int e = 0; e < E_DIM; e++) { acc += g_count[e]; g_offs[e + 1] = acc; }
    }
}

__global__ void scatter_kernel() {
    int p = blockIdx.x * 256 + threadIdx.x;
    if (p >= NPAIR) return;
    int e = g_expert_sel[p];
    int r = g_offs[e] + atomicAdd(&g_cursor[e], 1);
    g_row_token[r]  = p >> 1;
    g_row_weight[r] = g_pair_w[p];
    g_row_of_pair[p] = r;
}

// ---------------------------------------------------------------------------
// 4) weight conversion: fp32 [e][K][N] -> bf16 hi/lo K-major,
//    dst row = n*rowMul + rowAdd; dstSel resolves destination in device code.
// ---------------------------------------------------------------------------
__global__ void conv_transpose_kernel(const float* __restrict__ src,
                                      int dstSel,
                                      int K, int N, int dstERows,
                                      int rowMul, int rowAdd) {
    __nv_bfloat16* dh = (dstSel == 0) ? g_B1h : g_W2h;
    __nv_bfloat16* dl = (dstSel == 0) ? g_B1l : g_W2l;
    __shared__ float tile[32][33];
    int e = blockIdx.z;
    int k0 = blockIdx.y * 32, n0 = blockIdx.x * 32;
    const float* s = src + (size_t)e * K * N;
    int tx = threadIdx.x, ty = threadIdx.y;   // 32 x 8
#pragma unroll
    for (int i = 0; i < 32; i += 8)
        tile[ty + i][tx] = s[(size_t)(k0 + ty + i) * N + n0 + tx];
    __syncthreads();
#pragma unroll
    for (int i = 0; i < 32; i += 8) {
        float v = tile[tx][ty + i];
        __nv_bfloat16 hi = __float2bfloat16(v);
        __nv_bfloat16 lo = __float2bfloat16(v - __bfloat162float(hi));
        size_t row = (size_t)e * dstERows + (size_t)(n0 + ty + i) * rowMul + rowAdd;
        dh[row * K + k0 + tx] = hi;
        dl[row * K + k0 + tx] = lo;
    }
}

// ---------------------------------------------------------------------------
// 5) gather + split activations
// ---------------------------------------------------------------------------
__global__ void convA_kernel(const float* __restrict__ x) {
    int r = blockIdx.x;
    int c = threadIdx.x * 4;
    int token = g_row_token[r];
    float4 v = *(const float4*)(x + (size_t)token * H_DIM + c);
    size_t base = (size_t)r * H_DIM + c;
    float vv[4] = {v.x, v.y, v.z, v.w};
#pragma unroll
    for (int i = 0; i < 4; i++) {
        __nv_bfloat16 hi = __float2bfloat16(vv[i]);
        g_A1h[base + i] = hi;
        g_A1l[base + i] = __float2bfloat16(vv[i] - __bfloat162float(hi));
    }
}

// ---------------------------------------------------------------------------
// 6/7) Pipelined HMMA grouped GEMM: D[128x128] = A[128xK] @ B[128xK]^T,
//   split bf16 (3 products). ldmatrix fragments + 2-stage cp.async pipeline.
//   k-chunk = 16 halves, row pitch 48B (word stride 12 -> conflict-free).
//   Dynamic smem = 2 * 4 * 128 * 48 = 49152 B (default limit, no attribute).
//   SRC=0: A=g_A1h/l, B=g_B1h/l, FUSE epilogue -> g_Hh/l (silu(g)*u, hi/lo)
//   SRC=1: A=g_Hh/l,  B=g_W2h/l, weighted epilogue -> g_partial
// ---------------------------------------------------------------------------
#define ROW_P 48                 // bytes per row (32B data + 16B pad)
#define TILE_B (128 * ROW_P)     // 6144
#define STAGE_B (4 * TILE_B)     // 24576
#define SMEM_SZ (2 * STAGE_B)    // 49152 == default 48KB limit

template <int KCHUNKS, int ASTR, int BSTR, int BEROWS, bool FUSE, int SRC>
__global__ void __launch_bounds__(256, 1) mma_gemm() {
    const __nv_bfloat16* __restrict__ Ah = (SRC == 0) ? g_A1h : g_Hh;
    const __nv_bfloat16* __restrict__ Al = (SRC == 0) ? g_A1l : g_Hl;
    const __nv_bfloat16* __restrict__ Bh = (SRC == 0) ? g_B1h : g_W2h;
    const __nv_bfloat16* __restrict__ Bl = (SRC == 0) ? g_B1l : g_W2l;

    extern __shared__ char smem[];
    int e = blockIdx.z;
    int rowBeg = g_offs[e] + blockIdx.y * 128;
    int rowEnd = g_offs[e + 1];
    if (rowBeg >= rowEnd) return;
    int bx = blockIdx.x;
    int bRowBase = e * BEROWS + bx * 128;

    const int tid = threadIdx.x;
    const int wid = tid >> 5, lane = tid & 31;
    const int wm = wid >> 2, wn = wid & 3;
    uint32_t sb = smem_to_u32(smem);

    // ---- cp.async per-thread descriptors: 4 x 16B per stage ----
    // id = j*256+tid in 0..1023: arr=id>>8 (0:Ah 1:Al 2:Bh 3:Bl),
    // row=(id&255)>>1, c16=id&1
    const __nv_bfloat16* gptr[4];
    uint32_t dOff[4];
    uint32_t gsz[4];
#pragma unroll
    for (int j = 0; j < 4; j++) {
        int id  = j * 256 + tid;
        int arr = id >> 8;
        int q   = id & 255;
        int row = q >> 1;
        int c16 = q & 1;
        dOff[j] = arr * TILE_B + row * ROW_P + c16 * 16;
        if (arr < 2) {
            int grow = rowBeg + row;
            bool ok = grow < rowEnd;
            int cr = ok ? grow : rowBeg;
            const __nv_bfloat16* p = (arr == 0) ? Ah : Al;
            gptr[j] = p + (size_t)cr * ASTR + c16 * 8;
            gsz[j] = ok ? 16u : 0u;
        } else {
            const __nv_bfloat16* p = (arr == 2) ? Bh : Bl;
            gptr[j] = p + (size_t)(bRowBase + row) * BSTR + c16 * 8;
            gsz[j] = 16u;
        }
    }

    // ---- ldmatrix per-thread base offsets (validated fragment coordinates) ----
    // A x4: mat0=(m+0,k0) mat1=(m+8,k0) mat2=(m+0,k8) mat3=(m+8,k8)
    // B x4: mat0=(n+0,k0) mat1=(n+0,k8) mat2=(n+8,k0) mat3=(n+8,k8)
    int mat = lane >> 3, mrow = lane & 7;
    uint32_t aBase[4], bBase[2];
    {
        int rA  = wm * 64 + (mat & 1) * 8 + mrow;
        int kAb = (mat >> 1) * 16;              // bytes
#pragma unroll
        for (int mt = 0; mt < 4; mt++) aBase[mt] = (rA + mt * 16) * ROW_P + kAb;
        int rB  = wn * 32 + ((mat >> 1) & 1) * 8 + mrow;
        int kBb = (mat & 1) * 16;
#pragma unroll
        for (int nt = 0; nt < 2; nt++) bBase[nt] = (rB + nt * 16) * ROW_P + kBb;
    }

    float d[4][4][4];
#pragma unroll
    for (int i = 0; i < 4; i++)
#pragma unroll
        for (int j = 0; j < 4; j++)
#pragma unroll
            for (int c = 0; c < 4; c++) d[i][j][c] = 0.f;

    auto load_stage = [&](int s, int chunk) {
        uint32_t kByte = (uint32_t)chunk * 32;   // 16 halves
        uint32_t base = sb + s * STAGE_B;
#pragma unroll
        for (int j = 0; j < 4; j++)
            cp_async16(base + dOff[j], (const char*)gptr[j] + kByte, gsz[j]);
    };

    // prologue: stage 0 <- chunk 0
    load_stage(0, 0);
    cp_commit();

    for (int c = 0; c < KCHUNKS; c++) {
        if (c + 1 < KCHUNKS) load_stage((c + 1) & 1, c + 1);
        cp_commit();
        cp_wait<1>();            // chunk c's group complete
        __syncthreads();

        uint32_t stBase = sb + (c & 1) * STAGE_B;
        uint32_t ah[4][4], al[4][4], bh[2][4], bl[2][4];
#pragma unroll
        for (int mt = 0; mt < 4; mt++) {
            LDSM4(ah[mt], stBase + 0 * TILE_B + aBase[mt]);
            LDSM4(al[mt], stBase + 1 * TILE_B + aBase[mt]);
        }
#pragma unroll
        for (int nt = 0; nt < 2; nt++) {
            LDSM4(bh[nt], stBase + 2 * TILE_B + bBase[nt]);
            LDSM4(bl[nt], stBase + 3 * TILE_B + bBase[nt]);
        }
#pragma unroll
        for (int mt = 0; mt < 4; mt++) {
#pragma unroll
            for (int n8 = 0; n8 < 4; n8++) {
                int nt = n8 >> 1, o = (n8 & 1) * 2;
                MMA16816(d[mt][n8], ah[mt], bh[nt][o], bh[nt][o + 1]);
                MMA16816(d[mt][n8], ah[mt], bl[nt][o], bl[nt][o + 1]);
                MMA16816(d[mt][n8], al[mt], bh[nt][o], bh[nt][o + 1]);
            }
        }
        __syncthreads();
    }

    // ---- epilogue (identical to validated R12) ----
    if (FUSE) {
        __nv_bfloat16* shh = (__nv_bfloat16*)smem;           // [128][72] halves
        __nv_bfloat16* shl = shh + 128 * 72;
        int g4 = lane >> 2, t4 = lane & 3;
#pragma unroll
        for (int mt = 0; mt < 4; mt++) {
#pragma unroll
            for (int n8 = 0; n8 < 4; n8++) {
                int r0 = wm * 64 + mt * 16 + g4;
                int i0 = wn * 16 + n8 * 4 + t4;
                float g0 = d[mt][n8][0], u0 = d[mt][n8][1];
                float h0 = (g0 / (1.0f + expf(-g0))) * u0;
                __nv_bfloat16 hh0 = __float2bfloat16(h0);
                shh[r0 * 72 + i0] = hh0;
                shl[r0 * 72 + i0] = __float2bfloat16(h0 - __bfloat162float(hh0));
                float g1 = d[mt][n8][2], u1 = d[mt][n8][3];
                float h1 = (g1 / (1.0f + expf(-g1))) * u1;
                __nv_bfloat16 hh1 = __float2bfloat16(h1);
                shh[(r0 + 8) * 72 + i0] = hh1;
                shl[(r0 + 8) * 72 + i0] = __float2bfloat16(h1 - __bfloat162float(hh1));
            }
        }
        __syncthreads();
        int iBase = bx * 64;
#pragma unroll
        for (int j = 0; j < 8; j++) {
            int id = j * 256 + tid;          // 0..2047
            int arrSel = id >> 10;
            int q = id & 1023;
            int row = q >> 3;
            int cc = q & 7;
            int grow = rowBeg + row;
            if (grow < rowEnd) {
                const char* s = smem + (size_t)arrSel * (128 * 72 * 2) + row * 144 + cc * 16;
                __nv_bfloat16* dptr = (arrSel ? g_Hl : g_Hh) + (size_t)grow * I_DIM + iBase + cc * 8;
                *(uint4*)dptr = *(const uint4*)s;
            }
        }
    } else {
        int g4 = lane >> 2, t4 = lane & 3;
#pragma unroll
        for (int mt = 0; mt < 4; mt++) {
#pragma unroll
            for (int n8 = 0; n8 < 4; n8++) {
                int r0 = rowBeg + wm * 64 + mt * 16 + g4;
                int col = bx * 128 + wn * 32 + n8 * 8 + t4 * 2;
                if (r0 < rowEnd) {
                    float w = g_row_weight[r0];
                    float2 v = make_float2(w * d[mt][n8][0], w * d[mt][n8][1]);
                    *(float2*)&g_partial[(size_t)r0 * H_DIM + col] = v;
                }
                int r1 = r0 + 8;
                if (r1 < rowEnd) {
                    float w = g_row_weight[r1];
                    float2 v = make_float2(w * d[mt][n8][2], w * d[mt][n8][3]);
                    *(float2*)&g_partial[(size_t)r1 * H_DIM + col] = v;
                }
            }
        }
    }
}

// ---------------------------------------------------------------------------
// 8) combine
// ---------------------------------------------------------------------------
__global__ void combine_kernel(float* __restrict__ out) {
    int idx = blockIdx.x * 256 + threadIdx.x;
    if (idx >= T_DIM * (H_DIM / 4)) return;
    int t = idx >> 8;
    int j = (idx & 255) * 4;
    int r0 = g_row_of_pair[2 * t];
    int r1 = g_row_of_pair[2 * t + 1];
    float4 a = *(float4*)&g_partial[(size_t)r0 * H_DIM + j];
    float4 b = *(float4*)&g_partial[(size_t)r1 * H_DIM + j];
    float4 o;
    o.x = a.x + b.x; o.y = a.y + b.y; o.z = a.z + b.z; o.w = a.w + b.w;
    *(float4*)(out + (size_t)t * H_DIM + j) = o;
}

// ---------------------------------------------------------------------------
// launch
// ---------------------------------------------------------------------------
extern "C" void kernel_launch(void* const* d_in, const int* in_sizes, int n_in,
                              void* d_out, int out_size) {
    const float* x  = (const float*)d_in[0];
    const float* rw = (const float*)d_in[1];
    const float* gw = (const float*)d_in[2];
    const float* uw = (const float*)d_in[3];
    const float* ow = (const float*)d_in[4];
    float* out = (float*)d_out;

    int write_logits = (out_size >= T_DIM * H_DIM + T_DIM * E_DIM) ? 1 : 0;
    float* logits = out + (size_t)T_DIM * H_DIM;

    init_kernel<<<1, 32>>>();
    router_kernel<<<T_DIM / 8, 256>>>(x, rw, logits, write_logits);
    offsets_kernel<<<1, 32>>>();
    scatter_kernel<<<NPAIR / 256, 256>>>();

    // weight conversion (transpose + hi/lo split); gate/up interleaved
    dim3 cb(32, 8);
    conv_transpose_kernel<<<dim3(I_DIM / 32, H_DIM / 32, E_DIM), cb>>>(gw, 0, H_DIM, I_DIM, 4096, 2, 0);
    conv_transpose_kernel<<<dim3(I_DIM / 32, H_DIM / 32, E_DIM), cb>>>(uw, 0, H_DIM, I_DIM, 4096, 2, 1);
    conv_transpose_kernel<<<dim3(H_DIM / 32, I_DIM / 32, E_DIM), cb>>>(ow, 1, I_DIM, H_DIM, 1024, 1, 0);
    convA_kernel<<<NPAIR, 256>>>(x);

    // pipelined HMMA grouped GEMMs (48KB dynamic smem, no attribute needed)
    mma_gemm<64, 1024, 1024, 4096, true, 0><<<dim3(32, 32, E_DIM), 256, SMEM_SZ>>>();
    mma_gemm<128, 2048, 2048, 1024, false, 1><<<dim3(8, 32, E_DIM), 256, SMEM_SZ>>>();

    combine_kernel<<<(T_DIM * (H_DIM / 4) + 255) / 256, 256>>>(out);
}

// round 14
// speedup vs baseline: 2.2860x; 1.0299x over previous
#include <cuda_runtime.h>
#include <cuda_bf16.h>
#include <cstdint>
#include <math.h>

// Problem constants
#define T_DIM 4096
#define H_DIM 1024
#define I_DIM 2048
#define E_DIM 8
#define NPAIR (T_DIM * 2)   // 8192

// ---------------------------------------------------------------------------
// Static device scratch (no allocations allowed).
// NOTE: referenced ONLY from device code (host-passing these was the R7-R11 bug).
// ---------------------------------------------------------------------------
__device__ __nv_bfloat16 g_B1h[(size_t)E_DIM * 4096 * H_DIM];   // interleaved: row 2i=gate_i, 2i+1=up_i; K-major
__device__ __nv_bfloat16 g_B1l[(size_t)E_DIM * 4096 * H_DIM];
__device__ __nv_bfloat16 g_W2h[(size_t)E_DIM * H_DIM * I_DIM];  // [e][n=1024][k=2048]
__device__ __nv_bfloat16 g_W2l[(size_t)E_DIM * H_DIM * I_DIM];
__device__ __nv_bfloat16 g_A1h[(size_t)NPAIR * H_DIM];
__device__ __nv_bfloat16 g_A1l[(size_t)NPAIR * H_DIM];
__device__ __nv_bfloat16 g_Hh[(size_t)NPAIR * I_DIM];
__device__ __nv_bfloat16 g_Hl[(size_t)NPAIR * I_DIM];
__device__ float g_partial[(size_t)NPAIR * H_DIM];
__device__ int   g_count[E_DIM];
__device__ int   g_cursor[E_DIM];
__device__ int   g_offs[E_DIM + 1];
__device__ int   g_expert_sel[NPAIR];
__device__ float g_pair_w[NPAIR];
__device__ int   g_row_token[NPAIR];
__device__ float g_row_weight[NPAIR];
__device__ int   g_row_of_pair[NPAIR];

// ---------------------------------------------------------------------------
// PTX helpers (arch-portable: cp.async / ldmatrix / mma.sync)
// ---------------------------------------------------------------------------
__device__ __forceinline__ uint32_t smem_to_u32(const void* p) {
    uint32_t a;
    asm("{ .reg .u64 t; cvta.to.shared.u64 t, %1; cvt.u32.u64 %0, t; }" : "=r"(a) : "l"(p));
    return a;
}
__device__ __forceinline__ void cp_async16(uint32_t dst, const void* src, uint32_t srcBytes) {
    asm volatile("cp.async.cg.shared.global [%0], [%1], 16, %2;"
                 :: "r"(dst), "l"(src), "r"(srcBytes) : "memory");
}
__device__ __forceinline__ void cp_commit() {
    asm volatile("cp.async.commit_group;" ::: "memory");
}
template <int N>
__device__ __forceinline__ void cp_wait() {
    asm volatile("cp.async.wait_group %0;" :: "n"(N) : "memory");
}

#define LDSM4(r, addr) \
    asm volatile("ldmatrix.sync.aligned.m8n8.x4.shared.b16 {%0,%1,%2,%3}, [%4];" \
                 : "=r"((r)[0]), "=r"((r)[1]), "=r"((r)[2]), "=r"((r)[3]) : "r"(addr))

#define MMA16816(d, a, b0, b1) \
    asm volatile("mma.sync.aligned.m16n8k16.row.col.f32.bf16.bf16.f32 " \
                 "{%0,%1,%2,%3}, {%4,%5,%6,%7}, {%8,%9}, {%0,%1,%2,%3};" \
                 : "+f"((d)[0]), "+f"((d)[1]), "+f"((d)[2]), "+f"((d)[3]) \
                 : "r"((a)[0]), "r"((a)[1]), "r"((a)[2]), "r"((a)[3]), "r"(b0), "r"(b1))

// ---------------------------------------------------------------------------
// 0) init
// ---------------------------------------------------------------------------
__global__ void init_kernel() {
    int i = threadIdx.x;
    if (i < E_DIM) { g_count[i] = 0; g_cursor[i] = 0; }
}

// ---------------------------------------------------------------------------
// 1) router
// ---------------------------------------------------------------------------
__global__ void router_kernel(const float* __restrict__ x,
                              const float* __restrict__ rw,
                              float* __restrict__ logits_out,
                              int write_logits) {
    int t = blockIdx.x * 8 + (threadIdx.x >> 5);
    if (t >= T_DIM) return;
    int lane = threadIdx.x & 31;
    float acc[E_DIM];
#pragma unroll
    for (int e = 0; e < E_DIM; e++) acc[e] = 0.f;
    const float* xp = x + (size_t)t * H_DIM;
    for (int h = lane; h < H_DIM; h += 32) {
        float xv = xp[h];
        const float* r = rw + (size_t)h * E_DIM;
#pragma unroll
        for (int e = 0; e < E_DIM; e++) acc[e] += xv * r[e];
    }
#pragma unroll
    for (int e = 0; e < E_DIM; e++) {
#pragma unroll
        for (int off = 16; off; off >>= 1)
            acc[e] += __shfl_xor_sync(0xffffffffu, acc[e], off);
    }
    if (lane == 0) {
        if (write_logits) {
#pragma unroll
            for (int e = 0; e < E_DIM; e++) logits_out[(size_t)t * E_DIM + e] = acc[e];
        }
        int e0 = 0;
#pragma unroll
        for (int e = 1; e < E_DIM; e++) if (acc[e] > acc[e0]) e0 = e;
        int e1 = (e0 == 0) ? 1 : 0;
#pragma unroll
        for (int e = 0; e < E_DIM; e++)
            if (e != e0 && acc[e] > acc[e1]) e1 = e;
        float r1 = expf(acc[e1] - acc[e0]);
        float s  = 1.0f + r1;
        g_expert_sel[t * 2 + 0] = e0;
        g_expert_sel[t * 2 + 1] = e1;
        g_pair_w[t * 2 + 0] = 1.0f / s;
        g_pair_w[t * 2 + 1] = r1 / s;
        atomicAdd(&g_count[e0], 1);
        atomicAdd(&g_count[e1], 1);
    }
}

// ---------------------------------------------------------------------------
// 2) offsets  3) scatter
// ---------------------------------------------------------------------------
__global__ void offsets_kernel() {
    if (threadIdx.x == 0) {
        int acc = 0;
        g_offs[0] = 0;
#pragma unroll
        for (int e = 0; e < E_DIM; e++) { acc += g_count[e]; g_offs[e + 1] = acc; }
    }
}

__global__ void scatter_kernel() {
    int p = blockIdx.x * 256 + threadIdx.x;
    if (p >= NPAIR) return;
    int e = g_expert_sel[p];
    int r = g_offs[e] + atomicAdd(&g_cursor[e], 1);
    g_row_token[r]  = p >> 1;
    g_row_weight[r] = g_pair_w[p];
    g_row_of_pair[p] = r;
}

// ---------------------------------------------------------------------------
// 4) weight conversion: fp32 [e][K][N] -> bf16 hi/lo K-major,
//    dst row = n*rowMul + rowAdd; dstSel resolves destination in device code.
// ---------------------------------------------------------------------------
__global__ void conv_transpose_kernel(const float* __restrict__ src,
                                      int dstSel,
                                      int K, int N, int dstERows,
                                      int rowMul, int rowAdd) {
    __nv_bfloat16* dh = (dstSel == 0) ? g_B1h : g_W2h;
    __nv_bfloat16* dl = (dstSel == 0) ? g_B1l : g_W2l;
    __shared__ float tile[32][33];
    int e = blockIdx.z;
    int k0 = blockIdx.y * 32, n0 = blockIdx.x * 32;
    const float* s = src + (size_t)e * K * N;
    int tx = threadIdx.x, ty = threadIdx.y;   // 32 x 8
#pragma unroll
    for (int i = 0; i < 32; i += 8)
        tile[ty + i][tx] = s[(size_t)(k0 + ty + i) * N + n0 + tx];
    __syncthreads();
#pragma unroll
    for (int i = 0; i < 32; i += 8) {
        float v = tile[tx][ty + i];
        __nv_bfloat16 hi = __float2bfloat16(v);
        __nv_bfloat16 lo = __float2bfloat16(v - __bfloat162float(hi));
        size_t row = (size_t)e * dstERows + (size_t)(n0 + ty + i) * rowMul + rowAdd;
        dh[row * K + k0 + tx] = hi;
        dl[row * K + k0 + tx] = lo;
    }
}

// ---------------------------------------------------------------------------
// 5) gather + split activations
// ---------------------------------------------------------------------------
__global__ void convA_kernel(const float* __restrict__ x) {
    int r = blockIdx.x;
    int c = threadIdx.x * 4;
    int token = g_row_token[r];
    float4 v = *(const float4*)(x + (size_t)token * H_DIM + c);
    size_t base = (size_t)r * H_DIM + c;
    float vv[4] = {v.x, v.y, v.z, v.w};
#pragma unroll
    for (int i = 0; i < 4; i++) {
        __nv_bfloat16 hi = __float2bfloat16(vv[i]);
        g_A1h[base + i] = hi;
        g_A1l[base + i] = __float2bfloat16(vv[i] - __bfloat162float(hi));
    }
}

// ---------------------------------------------------------------------------
// 6/7) Pipelined HMMA grouped GEMM: D[128x128] = A[128xK] @ B[128xK]^T,
//   split bf16 (3 products). ldmatrix fragments + 4-stage cp.async pipeline.
//   k-chunk = 32 halves, row pitch 80B (word stride 20 -> conflict-free).
//   One __syncthreads per iteration (cutlass multistage ordering).
//   Dynamic smem = 4 * 4 * 128 * 80 = 163840 B (needs attribute; safe now
//   that the real R7 bug -- device symbols as host-side args -- is fixed).
//   SRC=0: A=g_A1h/l, B=g_B1h/l, FUSE epilogue -> g_Hh/l (silu(g)*u, hi/lo)
//   SRC=1: A=g_Hh/l,  B=g_W2h/l, weighted epilogue -> g_partial
// ---------------------------------------------------------------------------
#define NST 4
#define ROW_P 80                 // bytes per row (64B data + 16B pad)
#define TILE_B (128 * ROW_P)     // 10240
#define STAGE_B (4 * TILE_B)     // 40960
#define SMEM_SZ (NST * STAGE_B)  // 163840

template <int KCHUNKS, int ASTR, int BSTR, int BEROWS, bool FUSE, int SRC>
__global__ void __launch_bounds__(256, 1) mma_gemm() {
    const __nv_bfloat16* __restrict__ Ah = (SRC == 0) ? g_A1h : g_Hh;
    const __nv_bfloat16* __restrict__ Al = (SRC == 0) ? g_A1l : g_Hl;
    const __nv_bfloat16* __restrict__ Bh = (SRC == 0) ? g_B1h : g_W2h;
    const __nv_bfloat16* __restrict__ Bl = (SRC == 0) ? g_B1l : g_W2l;

    extern __shared__ char smem[];
    int e = blockIdx.z;
    int rowBeg = g_offs[e] + blockIdx.y * 128;
    int rowEnd = g_offs[e + 1];
    if (rowBeg >= rowEnd) return;
    int bx = blockIdx.x;
    int bRowBase = e * BEROWS + bx * 128;

    const int tid = threadIdx.x;
    const int wid = tid >> 5, lane = tid & 31;
    const int wm = wid >> 2, wn = wid & 3;
    uint32_t sb = smem_to_u32(smem);

    // ---- cp.async per-thread descriptors: 8 x 16B per stage ----
    // id = j*256+tid in 0..2047: arr=id>>9 (0:Ah 1:Al 2:Bh 3:Bl),
    // row=(id&511)>>2, c16=id&3   (4 x 16B = 64B data per row)
    const __nv_bfloat16* gptr[8];
    uint32_t dOff[8];
    uint32_t gsz[8];
#pragma unroll
    for (int j = 0; j < 8; j++) {
        int id  = j * 256 + tid;
        int arr = id >> 9;
        int q   = id & 511;
        int row = q >> 2;
        int c16 = q & 3;
        dOff[j] = arr * TILE_B + row * ROW_P + c16 * 16;
        if (arr < 2) {
            int grow = rowBeg + row;
            bool ok = grow < rowEnd;
            int cr = ok ? grow : rowBeg;
            const __nv_bfloat16* p = (arr == 0) ? Ah : Al;
            gptr[j] = p + (size_t)cr * ASTR + c16 * 8;
            gsz[j] = ok ? 16u : 0u;
        } else {
            const __nv_bfloat16* p = (arr == 2) ? Bh : Bl;
            gptr[j] = p + (size_t)(bRowBase + row) * BSTR + c16 * 8;
            gsz[j] = 16u;
        }
    }

    // ---- ldmatrix per-thread base offsets (validated fragment coordinates) ----
    int mat = lane >> 3, mrow = lane & 7;
    uint32_t aBase[4], bBase[2];
    {
        int rA  = wm * 64 + (mat & 1) * 8 + mrow;
        int kAb = (mat >> 1) * 16;              // bytes within 16-half subchunk
#pragma unroll
        for (int mt = 0; mt < 4; mt++) aBase[mt] = (rA + mt * 16) * ROW_P + kAb;
        int rB  = wn * 32 + ((mat >> 1) & 1) * 8 + mrow;
        int kBb = (mat & 1) * 16;
#pragma unroll
        for (int nt = 0; nt < 2; nt++) bBase[nt] = (rB + nt * 16) * ROW_P + kBb;
    }

    float d[4][4][4];
#pragma unroll
    for (int i = 0; i < 4; i++)
#pragma unroll
        for (int j = 0; j < 4; j++)
#pragma unroll
            for (int c = 0; c < 4; c++) d[i][j][c] = 0.f;

    auto load_stage = [&](int s, int chunk) {
        uint32_t kByte = (uint32_t)chunk * 64;   // 32 halves
        uint32_t base = sb + s * STAGE_B;
#pragma unroll
        for (int j = 0; j < 8; j++)
            cp_async16(base + dOff[j], (const char*)gptr[j] + kByte, gsz[j]);
    };

    // prologue: fill stages 0..NST-2 with chunks 0..NST-2
#pragma unroll
    for (int s = 0; s < NST - 1; s++) {
        load_stage(s, s);
        cp_commit();
    }

    for (int c = 0; c < KCHUNKS; c++) {
        cp_wait<NST - 2>();      // chunk c's group complete
        __syncthreads();

        // issue next-stage load first (overlaps with compute below);
        // target stage (c+NST-1)%NST was last read in iter c-1 -> safe.
        if (c + NST - 1 < KCHUNKS) load_stage((c + NST - 1) & (NST - 1), c + NST - 1);
        cp_commit();

        uint32_t stBase = sb + (c & (NST - 1)) * STAGE_B;
#pragma unroll
        for (int ks = 0; ks < 2; ks++) {
            uint32_t kadd = ks * 32;   // second 16-half subchunk at +32B
            uint32_t ah[4][4], al[4][4], bh[2][4], bl[2][4];
#pragma unroll
            for (int mt = 0; mt < 4; mt++) {
                LDSM4(ah[mt], stBase + 0 * TILE_B + aBase[mt] + kadd);
                LDSM4(al[mt], stBase + 1 * TILE_B + aBase[mt] + kadd);
            }
#pragma unroll
            for (int nt = 0; nt < 2; nt++) {
                LDSM4(bh[nt], stBase + 2 * TILE_B + bBase[nt] + kadd);
                LDSM4(bl[nt], stBase + 3 * TILE_B + bBase[nt] + kadd);
            }
#pragma unroll
            for (int mt = 0; mt < 4; mt++) {
#pragma unroll
                for (int n8 = 0; n8 < 4; n8++) {
                    int nt = n8 >> 1, o = (n8 & 1) * 2;
                    MMA16816(d[mt][n8], ah[mt], bh[nt][o], bh[nt][o + 1]);
                    MMA16816(d[mt][n8], ah[mt], bl[nt][o], bl[nt][o + 1]);
                    MMA16816(d[mt][n8], al[mt], bh[nt][o], bh[nt][o + 1]);
                }
            }
        }
    }
    __syncthreads();

    // ---- epilogue (identical to validated R12/R13) ----
    if (FUSE) {
        __nv_bfloat16* shh = (__nv_bfloat16*)smem;           // [128][72] halves
        __nv_bfloat16* shl = shh + 128 * 72;
        int g4 = lane >> 2, t4 = lane & 3;
#pragma unroll
        for (int mt = 0; mt < 4; mt++) {
#pragma unroll
            for (int n8 = 0; n8 < 4; n8++) {
                int r0 = wm * 64 + mt * 16 + g4;
                int i0 = wn * 16 + n8 * 4 + t4;
                float g0 = d[mt][n8][0], u0 = d[mt][n8][1];
                float h0 = (g0 / (1.0f + expf(-g0))) * u0;
                __nv_bfloat16 hh0 = __float2bfloat16(h0);
                shh[r0 * 72 + i0] = hh0;
                shl[r0 * 72 + i0] = __float2bfloat16(h0 - __bfloat162float(hh0));
                float g1 = d[mt][n8][2], u1 = d[mt][n8][3];
                float h1 = (g1 / (1.0f + expf(-g1))) * u1;
                __nv_bfloat16 hh1 = __float2bfloat16(h1);
                shh[(r0 + 8) * 72 + i0] = hh1;
                shl[(r0 + 8) * 72 + i0] = __float2bfloat16(h1 - __bfloat162float(hh1));
            }
        }
        __syncthreads();
        int iBase = bx * 64;
#pragma unroll
        for (int j = 0; j < 8; j++) {
            int id = j * 256 + tid;          // 0..2047
            int arrSel = id >> 10;
            int q = id & 1023;
            int row = q >> 3;
            int cc = q & 7;
            int grow = rowBeg + row;
            if (grow < rowEnd) {
                const char* s = smem + (size_t)arrSel * (128 * 72 * 2) + row * 144 + cc * 16;
                __nv_bfloat16* dptr = (arrSel ? g_Hl : g_Hh) + (size_t)grow * I_DIM + iBase + cc * 8;
                *(uint4*)dptr = *(const uint4*)s;
            }
        }
    } else {
        int g4 = lane >> 2, t4 = lane & 3;
#pragma unroll
        for (int mt = 0; mt < 4; mt++) {
#pragma unroll
            for (int n8 = 0; n8 < 4; n8++) {
                int r0 = rowBeg + wm * 64 + mt * 16 + g4;
                int col = bx * 128 + wn * 32 + n8 * 8 + t4 * 2;
                if (r0 < rowEnd) {
                    float w = g_row_weight[r0];
                    float2 v = make_float2(w * d[mt][n8][0], w * d[mt][n8][1]);
                    *(float2*)&g_partial[(size_t)r0 * H_DIM + col] = v;
                }
                int r1 = r0 + 8;
                if (r1 < rowEnd) {
                    float w = g_row_weight[r1];
                    float2 v = make_float2(w * d[mt][n8][2], w * d[mt][n8][3]);
                    *(float2*)&g_partial[(size_t)r1 * H_DIM + col] = v;
                }
            }
        }
    }
}

// ---------------------------------------------------------------------------
// 8) combine
// ---------------------------------------------------------------------------
__global__ void combine_kernel(float* __restrict__ out) {
    int idx = blockIdx.x * 256 + threadIdx.x;
    if (idx >= T_DIM * (H_DIM / 4)) return;
    int t = idx >> 8;
    int j = (idx & 255) * 4;
    int r0 = g_row_of_pair[2 * t];
    int r1 = g_row_of_pair[2 * t + 1];
    float4 a = *(float4*)&g_partial[(size_t)r0 * H_DIM + j];
    float4 b = *(float4*)&g_partial[(size_t)r1 * H_DIM + j];
    float4 o;
    o.x = a.x + b.x; o.y = a.y + b.y; o.z = a.z + b.z; o.w = a.w + b.w;
    *(float4*)(out + (size_t)t * H_DIM + j) = o;
}

// ---------------------------------------------------------------------------
// launch
// ---------------------------------------------------------------------------
extern "C" void kernel_launch(void* const* d_in, const int* in_sizes, int n_in,
                              void* d_out, int out_size) {
    const float* x  = (const float*)d_in[0];
    const float* rw = (const float*)d_in[1];
    const float* gw = (const float*)d_in[2];
    const float* uw = (const float*)d_in[3];
    const float* ow = (const float*)d_in[4];
    float* out = (float*)d_out;

    int write_logits = (out_size >= T_DIM * H_DIM + T_DIM * E_DIM) ? 1 : 0;
    float* logits = out + (size_t)T_DIM * H_DIM;

    // >48KB dynamic smem opt-in (safe: the R7-era failure was the
    // device-symbol-argument bug, not this attribute).
    cudaFuncSetAttribute(mma_gemm<32, 1024, 1024, 4096, true, 0>,
                         cudaFuncAttributeMaxDynamicSharedMemorySize, SMEM_SZ);
    cudaFuncSetAttribute(mma_gemm<64, 2048, 2048, 1024, false, 1>,
                         cudaFuncAttributeMaxDynamicSharedMemorySize, SMEM_SZ);

    init_kernel<<<1, 32>>>();
    router_kernel<<<T_DIM / 8, 256>>>(x, rw, logits, write_logits);
    offsets_kernel<<<1, 32>>>();
    scatter_kernel<<<NPAIR / 256, 256>>>();

    // weight conversion (transpose + hi/lo split); gate/up interleaved
    dim3 cb(32, 8);
    conv_transpose_kernel<<<dim3(I_DIM / 32, H_DIM / 32, E_DIM), cb>>>(gw, 0, H_DIM, I_DIM, 4096, 2, 0);
    conv_transpose_kernel<<<dim3(I_DIM / 32, H_DIM / 32, E_DIM), cb>>>(uw, 0, H_DIM, I_DIM, 4096, 2, 1);
    conv_transpose_kernel<<<dim3(H_DIM / 32, I_DIM / 32, E_DIM), cb>>>(ow, 1, I_DIM, H_DIM, 1024, 1, 0);
    convA_kernel<<<NPAIR, 256>>>(x);

    // pipelined HMMA grouped GEMMs (160KB dynamic smem, 4 stages)
    mma_gemm<32, 1024, 1024, 4096, true, 0><<<dim3(32, 32, E_DIM), 256, SMEM_SZ>>>();
    mma_gemm<64, 2048, 2048, 1024, false, 1><<<dim3(8, 32, E_DIM), 256, SMEM_SZ>>>();

    combine_kernel<<<(T_DIM * (H_DIM / 4) + 255) / 256, 256>>>(out);
}

// round 15
// speedup vs baseline: 3.0155x; 1.3191x over previous
#include <cuda_runtime.h>
#include <cuda_bf16.h>
#include <cstdint>
#include <math.h>

// Problem constants
#define T_DIM 4096
#define H_DIM 1024
#define I_DIM 2048
#define E_DIM 8
#define NPAIR (T_DIM * 2)   // 8192

// ---------------------------------------------------------------------------
// Static device scratch (no allocations allowed).
// Referenced ONLY from device code (host-passing these was the R7-R11 bug).
// All tf32 values stored as fp32 bit patterns (low 13 mantissa bits zero).
// ---------------------------------------------------------------------------
__device__ float g_B1[(size_t)E_DIM * 4096 * H_DIM];   // interleaved rows: 2i=gate_i, 2i+1=up_i; K-major
__device__ float g_W2[(size_t)E_DIM * H_DIM * I_DIM];  // [e][n=1024][k=2048]
__device__ float g_A1[(size_t)NPAIR * H_DIM];
__device__ float g_H [(size_t)NPAIR * I_DIM];
__device__ float g_partial[(size_t)NPAIR * H_DIM];
__device__ int   g_count[E_DIM];
__device__ int   g_cursor[E_DIM];
__device__ int   g_offs[E_DIM + 1];
__device__ int   g_expert_sel[NPAIR];
__device__ float g_pair_w[NPAIR];
__device__ int   g_row_token[NPAIR];
__device__ float g_row_weight[NPAIR];
__device__ int   g_row_of_pair[NPAIR];

// ---------------------------------------------------------------------------
// PTX helpers (arch-portable: cp.async / ldmatrix / mma.sync tf32)
// ---------------------------------------------------------------------------
__device__ __forceinline__ uint32_t smem_to_u32(const void* p) {
    uint32_t a;
    asm("{ .reg .u64 t; cvta.to.shared.u64 t, %1; cvt.u32.u64 %0, t; }" : "=r"(a) : "l"(p));
    return a;
}
__device__ __forceinline__ void cp_async16(uint32_t dst, const void* src, uint32_t srcBytes) {
    asm volatile("cp.async.cg.shared.global [%0], [%1], 16, %2;"
                 :: "r"(dst), "l"(src), "r"(srcBytes) : "memory");
}
__device__ __forceinline__ void cp_commit() {
    asm volatile("cp.async.commit_group;" ::: "memory");
}
template <int N>
__device__ __forceinline__ void cp_wait() {
    asm volatile("cp.async.wait_group %0;" :: "n"(N) : "memory");
}
__device__ __forceinline__ float tf32_rna(float v) {
    uint32_t o;
    asm("cvt.rna.tf32.f32 %0, %1;" : "=r"(o) : "f"(v));
    return __uint_as_float(o);
}

#define LDSM4(r, addr) \
    asm volatile("ldmatrix.sync.aligned.m8n8.x4.shared.b16 {%0,%1,%2,%3}, [%4];" \
                 : "=r"((r)[0]), "=r"((r)[1]), "=r"((r)[2]), "=r"((r)[3]) : "r"(addr))

#define MMATF32(d, a, b0, b1) \
    asm volatile("mma.sync.aligned.m16n8k8.row.col.f32.tf32.tf32.f32 " \
                 "{%0,%1,%2,%3}, {%4,%5,%6,%7}, {%8,%9}, {%0,%1,%2,%3};" \
                 : "+f"((d)[0]), "+f"((d)[1]), "+f"((d)[2]), "+f"((d)[3]) \
                 : "r"((a)[0]), "r"((a)[1]), "r"((a)[2]), "r"((a)[3]), "r"(b0), "r"(b1))

// ---------------------------------------------------------------------------
// 0) init
// ---------------------------------------------------------------------------
__global__ void init_kernel() {
    int i = threadIdx.x;
    if (i < E_DIM) { g_count[i] = 0; g_cursor[i] = 0; }
}

// ---------------------------------------------------------------------------
// 1) router (fp32 exact — routing decisions unaffected by tf32 FFN)
// ---------------------------------------------------------------------------
__global__ void router_kernel(const float* __restrict__ x,
                              const float* __restrict__ rw,
                              float* __restrict__ logits_out,
                              int write_logits) {
    int t = blockIdx.x * 8 + (threadIdx.x >> 5);
    if (t >= T_DIM) return;
    int lane = threadIdx.x & 31;
    float acc[E_DIM];
#pragma unroll
    for (int e = 0; e < E_DIM; e++) acc[e] = 0.f;
    const float* xp = x + (size_t)t * H_DIM;
    for (int h = lane; h < H_DIM; h += 32) {
        float xv = xp[h];
        const float* r = rw + (size_t)h * E_DIM;
#pragma unroll
        for (int e = 0; e < E_DIM; e++) acc[e] += xv * r[e];
    }
#pragma unroll
    for (int e = 0; e < E_DIM; e++) {
#pragma unroll
        for (int off = 16; off; off >>= 1)
            acc[e] += __shfl_xor_sync(0xffffffffu, acc[e], off);
    }
    if (lane == 0) {
        if (write_logits) {
#pragma unroll
            for (int e = 0; e < E_DIM; e++) logits_out[(size_t)t * E_DIM + e] = acc[e];
        }
        int e0 = 0;
#pragma unroll
        for (int e = 1; e < E_DIM; e++) if (acc[e] > acc[e0]) e0 = e;
        int e1 = (e0 == 0) ? 1 : 0;
#pragma unroll
        for (int e = 0; e < E_DIM; e++)
            if (e != e0 && acc[e] > acc[e1]) e1 = e;
        float r1 = expf(acc[e1] - acc[e0]);
        float s  = 1.0f + r1;
        g_expert_sel[t * 2 + 0] = e0;
        g_expert_sel[t * 2 + 1] = e1;
        g_pair_w[t * 2 + 0] = 1.0f / s;
        g_pair_w[t * 2 + 1] = r1 / s;
        atomicAdd(&g_count[e0], 1);
        atomicAdd(&g_count[e1], 1);
    }
}

// ---------------------------------------------------------------------------
// 2) offsets  3) scatter
// ---------------------------------------------------------------------------
__global__ void offsets_kernel() {
    if (threadIdx.x == 0) {
        int acc = 0;
        g_offs[0] = 0;
#pragma unroll
        for (int e = 0; e < E_DIM; e++) { acc += g_count[e]; g_offs[e + 1] = acc; }
    }
}

__global__ void scatter_kernel() {
    int p = blockIdx.x * 256 + threadIdx.x;
    if (p >= NPAIR) return;
    int e = g_expert_sel[p];
    int r = g_offs[e] + atomicAdd(&g_cursor[e], 1);
    g_row_token[r]  = p >> 1;
    g_row_weight[r] = g_pair_w[p];
    g_row_of_pair[p] = r;
}

// ---------------------------------------------------------------------------
// 4) weight conversion: fp32 [e][K][N] -> tf32(rna) K-major,
//    dst row = n*rowMul + rowAdd; dstSel resolves destination in device code.
// ---------------------------------------------------------------------------
__global__ void conv_transpose_kernel(const float* __restrict__ src,
                                      int dstSel,
                                      int K, int N, int dstERows,
                                      int rowMul, int rowAdd) {
    float* dd = (dstSel == 0) ? g_B1 : g_W2;
    __shared__ float tile[32][33];
    int e = blockIdx.z;
    int k0 = blockIdx.y * 32, n0 = blockIdx.x * 32;
    const float* s = src + (size_t)e * K * N;
    int tx = threadIdx.x, ty = threadIdx.y;   // 32 x 8
#pragma unroll
    for (int i = 0; i < 32; i += 8)
        tile[ty + i][tx] = s[(size_t)(k0 + ty + i) * N + n0 + tx];
    __syncthreads();
#pragma unroll
    for (int i = 0; i < 32; i += 8) {
        float v = tf32_rna(tile[tx][ty + i]);
        size_t row = (size_t)e * dstERows + (size_t)(n0 + ty + i) * rowMul + rowAdd;
        dd[row * K + k0 + tx] = v;
    }
}

// ---------------------------------------------------------------------------
// 5) gather + round activations
// ---------------------------------------------------------------------------
__global__ void convA_kernel(const float* __restrict__ x) {
    int r = blockIdx.x;
    int c = threadIdx.x * 4;
    int token = g_row_token[r];
    float4 v = *(const float4*)(x + (size_t)token * H_DIM + c);
    v.x = tf32_rna(v.x); v.y = tf32_rna(v.y);
    v.z = tf32_rna(v.z); v.w = tf32_rna(v.w);
    *(float4*)(g_A1 + (size_t)r * H_DIM + c) = v;
}

// ---------------------------------------------------------------------------
// 6/7) Pipelined tf32 MMA grouped GEMM: D[128x128] = A[128xK] @ B[128xK]^T.
//   Single-product tf32 (m16n8k8), ldmatrix.b16 fragment loads (tf32 trick:
//   each 8x8 b16 mat = 8x4 tf32 words; same lane->address formulas as the
//   validated bf16 code, pitch 144B). 4-stage cp.async, k-chunk = 32 floats.
//   Dynamic smem = 4 * 2 * 128 * 144 = 147456 B (attribute opt-in).
//   SRC=0: A=g_A1, B=g_B1, FUSE epilogue -> g_H = rna(silu(g)*u)
//   SRC=1: A=g_H,  B=g_W2, weighted epilogue -> g_partial
// ---------------------------------------------------------------------------
#define NST 4
#define ROW_P 144                // bytes per row (128B data + 16B pad; 9x16B)
#define TILE_B (128 * ROW_P)     // 18432
#define STAGE_B (2 * TILE_B)     // 36864
#define SMEM_SZ (NST * STAGE_B)  // 147456

template <int KCHUNKS, int ASTR, int BSTR, int BEROWS, bool FUSE, int SRC>
__global__ void __launch_bounds__(256, 1) mma_gemm() {
    const float* __restrict__ Ap = (SRC == 0) ? g_A1 : g_H;
    const float* __restrict__ Bp = (SRC == 0) ? g_B1 : g_W2;

    extern __shared__ char smem[];
    int e = blockIdx.z;
    int rowBeg = g_offs[e] + blockIdx.y * 128;
    int rowEnd = g_offs[e + 1];
    if (rowBeg >= rowEnd) return;
    int bx = blockIdx.x;
    int bRowBase = e * BEROWS + bx * 128;

    const int tid = threadIdx.x;
    const int wid = tid >> 5, lane = tid & 31;
    const int wm = wid >> 2, wn = wid & 3;
    uint32_t sb = smem_to_u32(smem);

    // ---- cp.async per-thread descriptors: 8 x 16B per stage ----
    // id = j*256+tid in 0..2047: arr=id>>10 (0:A 1:B), row=(id&1023)>>3, c16=id&7
    const float* gptr[8];
    uint32_t dOff[8];
    uint32_t gsz[8];
#pragma unroll
    for (int j = 0; j < 8; j++) {
        int id  = j * 256 + tid;
        int arr = id >> 10;
        int q   = id & 1023;
        int row = q >> 3;
        int c16 = q & 7;
        dOff[j] = arr * TILE_B + row * ROW_P + c16 * 16;
        if (arr == 0) {
            int grow = rowBeg + row;
            bool ok = grow < rowEnd;
            int cr = ok ? grow : rowBeg;
            gptr[j] = Ap + (size_t)cr * ASTR + c16 * 4;
            gsz[j] = ok ? 16u : 0u;
        } else {
            gptr[j] = Bp + (size_t)(bRowBase + row) * BSTR + c16 * 4;
            gsz[j] = 16u;
        }
    }

    // ---- ldmatrix per-thread base offsets (validated formulas, 32-bit elems) ----
    // A x4 regs -> a0..a3 of m16k8:  mat0=(m+0,k0-3) mat1=(m+8,k0-3)
    //                                mat2=(m+0,k4-7) mat3=(m+8,k4-7)
    // B x4 regs -> n8-group 0: {b0=(n0-7,k0-3), b1=(n0-7,k4-7)},
    //              n8-group 1: {b0=(n8-15,k0-3), b1=(n8-15,k4-7)}
    int mat = lane >> 3, mrow = lane & 7;
    uint32_t aBase[4], bBase[2];
    {
        int rA  = wm * 64 + (mat & 1) * 8 + mrow;
        int kAb = (mat >> 1) * 16;              // bytes (4 floats)
#pragma unroll
        for (int mt = 0; mt < 4; mt++) aBase[mt] = (rA + mt * 16) * ROW_P + kAb;
        int rB  = wn * 32 + ((mat >> 1) & 1) * 8 + mrow;
        int kBb = (mat & 1) * 16;
#pragma unroll
        for (int nt = 0; nt < 2; nt++) bBase[nt] = (rB + nt * 16) * ROW_P + kBb;
    }

    float d[4][4][4];
#pragma unroll
    for (int i = 0; i < 4; i++)
#pragma unroll
        for (int j = 0; j < 4; j++)
#pragma unroll
            for (int c = 0; c < 4; c++) d[i][j][c] = 0.f;

    auto load_stage = [&](int s, int chunk) {
        uint32_t kByte = (uint32_t)chunk * 128;  // 32 floats
        uint32_t base = sb + s * STAGE_B;
#pragma unroll
        for (int j = 0; j < 8; j++)
            cp_async16(base + dOff[j], (const char*)gptr[j] + kByte, gsz[j]);
    };

    // prologue: fill stages 0..NST-2 with chunks 0..NST-2
#pragma unroll
    for (int s = 0; s < NST - 1; s++) {
        load_stage(s, s);
        cp_commit();
    }

    for (int c = 0; c < KCHUNKS; c++) {
        cp_wait<NST - 2>();
        __syncthreads();

        if (c + NST - 1 < KCHUNKS) load_stage((c + NST - 1) & (NST - 1), c + NST - 1);
        cp_commit();

        uint32_t stA = sb + (c & (NST - 1)) * STAGE_B;
        uint32_t stB = stA + TILE_B;
#pragma unroll
        for (int s = 0; s < 4; s++) {            // 4 k8 steps per 32-float chunk
            uint32_t kadd = s * 32;              // 8 floats
            uint32_t a[4][4], b[2][4];
#pragma unroll
            for (int mt = 0; mt < 4; mt++)
                LDSM4(a[mt], stA + aBase[mt] + kadd);
#pragma unroll
            for (int nt = 0; nt < 2; nt++)
                LDSM4(b[nt], stB + bBase[nt] + kadd);
#pragma unroll
            for (int mt = 0; mt < 4; mt++) {
#pragma unroll
                for (int n8 = 0; n8 < 4; n8++) {
                    int nt = n8 >> 1, g = (n8 & 1) * 2;
                    MMATF32(d[mt][n8], a[mt], b[nt][g], b[nt][g + 1]);
                }
            }
        }
    }
    __syncthreads();

    // ---- epilogue (D fragment layout identical to validated bf16 path) ----
    if (FUSE) {
        // interleaved B: even col=gate_i, odd col=up_i; i = wn*16 + n8*4 + t4
        float* sh = (float*)smem;                // [128][72] floats
        int g4 = lane >> 2, t4 = lane & 3;
#pragma unroll
        for (int mt = 0; mt < 4; mt++) {
#pragma unroll
            for (int n8 = 0; n8 < 4; n8++) {
                int r0 = wm * 64 + mt * 16 + g4;
                int i0 = wn * 16 + n8 * 4 + t4;
                float g0 = d[mt][n8][0], u0 = d[mt][n8][1];
                sh[r0 * 72 + i0] = tf32_rna((g0 / (1.0f + expf(-g0))) * u0);
                float g1 = d[mt][n8][2], u1 = d[mt][n8][3];
                sh[(r0 + 8) * 72 + i0] = tf32_rna((g1 / (1.0f + expf(-g1))) * u1);
            }
        }
        __syncthreads();
        int iBase = bx * 64;
#pragma unroll
        for (int j = 0; j < 8; j++) {
            int id = j * 256 + tid;          // 0..2047 = 128 rows x 16 chunks16B
            int row = id >> 4;
            int cc = id & 15;
            int grow = rowBeg + row;
            if (grow < rowEnd) {
                const char* s = smem + row * 288 + cc * 16;
                float* dptr = g_H + (size_t)grow * I_DIM + iBase + cc * 4;
                *(uint4*)dptr = *(const uint4*)s;
            }
        }
    } else {
        int g4 = lane >> 2, t4 = lane & 3;
#pragma unroll
        for (int mt = 0; mt < 4; mt++) {
#pragma unroll
            for (int n8 = 0; n8 < 4; n8++) {
                int r0 = rowBeg + wm * 64 + mt * 16 + g4;
                int col = bx * 128 + wn * 32 + n8 * 8 + t4 * 2;
                if (r0 < rowEnd) {
                    float w = g_row_weight[r0];
                    float2 v = make_float2(w * d[mt][n8][0], w * d[mt][n8][1]);
                    *(float2*)&g_partial[(size_t)r0 * H_DIM + col] = v;
                }
                int r1 = r0 + 8;
                if (r1 < rowEnd) {
                    float w = g_row_weight[r1];
                    float2 v = make_float2(w * d[mt][n8][2], w * d[mt][n8][3]);
                    *(float2*)&g_partial[(size_t)r1 * H_DIM + col] = v;
                }
            }
        }
    }
}

// ---------------------------------------------------------------------------
// 8) combine
// ---------------------------------------------------------------------------
__global__ void combine_kernel(float* __restrict__ out) {
    int idx = blockIdx.x * 256 + threadIdx.x;
    if (idx >= T_DIM * (H_DIM / 4)) return;
    int t = idx >> 8;
    int j = (idx & 255) * 4;
    int r0 = g_row_of_pair[2 * t];
    int r1 = g_row_of_pair[2 * t + 1];
    float4 a = *(float4*)&g_partial[(size_t)r0 * H_DIM + j];
    float4 b = *(float4*)&g_partial[(size_t)r1 * H_DIM + j];
    float4 o;
    o.x = a.x + b.x; o.y = a.y + b.y; o.z = a.z + b.z; o.w = a.w + b.w;
    *(float4*)(out + (size_t)t * H_DIM + j) = o;
}

// ---------------------------------------------------------------------------
// launch
// ---------------------------------------------------------------------------
extern "C" void kernel_launch(void* const* d_in, const int* in_sizes, int n_in,
                              void* d_out, int out_size) {
    const float* x  = (const float*)d_in[0];
    const float* rw = (const float*)d_in[1];
    const float* gw = (const float*)d_in[2];
    const float* uw = (const float*)d_in[3];
    const float* ow = (const float*)d_in[4];
    float* out = (float*)d_out;

    int write_logits = (out_size >= T_DIM * H_DIM + T_DIM * E_DIM) ? 1 : 0;
    float* logits = out + (size_t)T_DIM * H_DIM;

    cudaFuncSetAttribute(mma_gemm<32, 1024, 1024, 4096, true, 0>,
                         cudaFuncAttributeMaxDynamicSharedMemorySize, SMEM_SZ);
    cudaFuncSetAttribute(mma_gemm<64, 2048, 2048, 1024, false, 1>,
                         cudaFuncAttributeMaxDynamicSharedMemorySize, SMEM_SZ);

    init_kernel<<<1, 32>>>();
    router_kernel<<<T_DIM / 8, 256>>>(x, rw, logits, write_logits);
    offsets_kernel<<<1, 32>>>();
    scatter_kernel<<<NPAIR / 256, 256>>>();

    // weight conversion (transpose + tf32 rna); gate/up interleaved
    dim3 cb(32, 8);
    conv_transpose_kernel<<<dim3(I_DIM / 32, H_DIM / 32, E_DIM), cb>>>(gw, 0, H_DIM, I_DIM, 4096, 2, 0);
    conv_transpose_kernel<<<dim3(I_DIM / 32, H_DIM / 32, E_DIM), cb>>>(uw, 0, H_DIM, I_DIM, 4096, 2, 1);
    conv_transpose_kernel<<<dim3(H_DIM / 32, I_DIM / 32, E_DIM), cb>>>(ow, 1, I_DIM, H_DIM, 1024, 1, 0);
    convA_kernel<<<NPAIR, 256>>>(x);

    // pipelined tf32 grouped GEMMs (144KB dynamic smem, 4 stages)
    mma_gemm<32, 1024, 1024, 4096, true, 0><<<dim3(32, 32, E_DIM), 256, SMEM_SZ>>>();
    mma_gemm<64, 2048, 2048, 1024, false, 1><<<dim3(8, 32, E_DIM), 256, SMEM_SZ>>>();

    combine_kernel<<<(T_DIM * (H_DIM / 4) + 255) / 256, 256>>>(out);
}

// round 16
// speedup vs baseline: 3.6611x; 1.2141x over previous
#include <cuda_runtime.h>
#include <cuda_bf16.h>
#include <cstdint>
#include <math.h>

// Problem constants
#define T_DIM 4096
#define H_DIM 1024
#define I_DIM 2048
#define E_DIM 8
#define NPAIR (T_DIM * 2)   // 8192

// ---------------------------------------------------------------------------
// Static device scratch (no allocations allowed).
// Referenced ONLY from device code (host-passing these was the R7-R11 bug).
// All tf32 values stored as fp32 bit patterns (low 13 mantissa bits zero).
// ---------------------------------------------------------------------------
__device__ float g_B1[(size_t)E_DIM * 4096 * H_DIM];   // interleaved rows: 2i=gate_i, 2i+1=up_i; K-major
__device__ float g_W2[(size_t)E_DIM * H_DIM * I_DIM];  // [e][n=1024][k=2048]
__device__ float g_A1[(size_t)NPAIR * H_DIM];
__device__ float g_H [(size_t)NPAIR * I_DIM];
__device__ float g_partial[(size_t)NPAIR * H_DIM];
__device__ int   g_count[E_DIM];
__device__ int   g_cursor[E_DIM];
__device__ int   g_offs[E_DIM + 1];
__device__ int   g_expert_sel[NPAIR];
__device__ float g_pair_w[NPAIR];
__device__ int   g_row_token[NPAIR];
__device__ float g_row_weight[NPAIR];
__device__ int   g_row_of_pair[NPAIR];

// ---------------------------------------------------------------------------
// PTX helpers (arch-portable: cp.async / ldmatrix / mma.sync tf32)
// ---------------------------------------------------------------------------
__device__ __forceinline__ uint32_t smem_to_u32(const void* p) {
    uint32_t a;
    asm("{ .reg .u64 t; cvta.to.shared.u64 t, %1; cvt.u32.u64 %0, t; }" : "=r"(a) : "l"(p));
    return a;
}
__device__ __forceinline__ void cp_async16(uint32_t dst, const void* src, uint32_t srcBytes) {
    asm volatile("cp.async.cg.shared.global [%0], [%1], 16, %2;"
                 :: "r"(dst), "l"(src), "r"(srcBytes) : "memory");
}
__device__ __forceinline__ void cp_commit() {
    asm volatile("cp.async.commit_group;" ::: "memory");
}
template <int N>
__device__ __forceinline__ void cp_wait() {
    asm volatile("cp.async.wait_group %0;" :: "n"(N) : "memory");
}
__device__ __forceinline__ float tf32_rna(float v) {
    uint32_t o;
    asm("cvt.rna.tf32.f32 %0, %1;" : "=r"(o) : "f"(v));
    return __uint_as_float(o);
}

#define LDSM4(r, addr) \
    asm volatile("ldmatrix.sync.aligned.m8n8.x4.shared.b16 {%0,%1,%2,%3}, [%4];" \
                 : "=r"((r)[0]), "=r"((r)[1]), "=r"((r)[2]), "=r"((r)[3]) : "r"(addr))

#define MMATF32(d, a, b0, b1) \
    asm volatile("mma.sync.aligned.m16n8k8.row.col.f32.tf32.tf32.f32 " \
                 "{%0,%1,%2,%3}, {%4,%5,%6,%7}, {%8,%9}, {%0,%1,%2,%3};" \
                 : "+f"((d)[0]), "+f"((d)[1]), "+f"((d)[2]), "+f"((d)[3]) \
                 : "r"((a)[0]), "r"((a)[1]), "r"((a)[2]), "r"((a)[3]), "r"(b0), "r"(b1))

// ---------------------------------------------------------------------------
// 0) init
// ---------------------------------------------------------------------------
__global__ void init_kernel() {
    int i = threadIdx.x;
    if (i < E_DIM) { g_count[i] = 0; g_cursor[i] = 0; }
}

// ---------------------------------------------------------------------------
// 1) router (fp32 exact)
// ---------------------------------------------------------------------------
__global__ void router_kernel(const float* __restrict__ x,
                              const float* __restrict__ rw,
                              float* __restrict__ logits_out,
                              int write_logits) {
    int t = blockIdx.x * 8 + (threadIdx.x >> 5);
    if (t >= T_DIM) return;
    int lane = threadIdx.x & 31;
    float acc[E_DIM];
#pragma unroll
    for (int e = 0; e < E_DIM; e++) acc[e] = 0.f;
    const float* xp = x + (size_t)t * H_DIM;
    for (int h = lane; h < H_DIM; h += 32) {
        float xv = xp[h];
        const float* r = rw + (size_t)h * E_DIM;
#pragma unroll
        for (int e = 0; e < E_DIM; e++) acc[e] += xv * r[e];
    }
#pragma unroll
    for (int e = 0; e < E_DIM; e++) {
#pragma unroll
        for (int off = 16; off; off >>= 1)
            acc[e] += __shfl_xor_sync(0xffffffffu, acc[e], off);
    }
    if (lane == 0) {
        if (write_logits) {
#pragma unroll
            for (int e = 0; e < E_DIM; e++) logits_out[(size_t)t * E_DIM + e] = acc[e];
        }
        int e0 = 0;
#pragma unroll
        for (int e = 1; e < E_DIM; e++) if (acc[e] > acc[e0]) e0 = e;
        int e1 = (e0 == 0) ? 1 : 0;
#pragma unroll
        for (int e = 0; e < E_DIM; e++)
            if (e != e0 && acc[e] > acc[e1]) e1 = e;
        float r1 = expf(acc[e1] - acc[e0]);
        float s  = 1.0f + r1;
        g_expert_sel[t * 2 + 0] = e0;
        g_expert_sel[t * 2 + 1] = e1;
        g_pair_w[t * 2 + 0] = 1.0f / s;
        g_pair_w[t * 2 + 1] = r1 / s;
        atomicAdd(&g_count[e0], 1);
        atomicAdd(&g_count[e1], 1);
    }
}

// ---------------------------------------------------------------------------
// 2) offsets  3) scatter
// ---------------------------------------------------------------------------
__global__ void offsets_kernel() {
    if (threadIdx.x == 0) {
        int acc = 0;
        g_offs[0] = 0;
#pragma unroll
        for (int e = 0; e < E_DIM; e++) { acc += g_count[e]; g_offs[e + 1] = acc; }
    }
}

__global__ void scatter_kernel() {
    int p = blockIdx.x * 256 + threadIdx.x;
    if (p >= NPAIR) return;
    int e = g_expert_sel[p];
    int r = g_offs[e] + atomicAdd(&g_cursor[e], 1);
    g_row_token[r]  = p >> 1;
    g_row_weight[r] = g_pair_w[p];
    g_row_of_pair[p] = r;
}

// ---------------------------------------------------------------------------
// 4a) B1 conversion (gate+up merged): fp32 [e][K=1024][N=2048] -> tf32(rna),
//     K-major interleaved rows (2n = gate_n, 2n+1 = up_n).
//     grid.x: 0..31 -> gate tile, 32..63 -> up tile.
// ---------------------------------------------------------------------------
__global__ void conv_b1_kernel(const float* __restrict__ gw,
                               const float* __restrict__ uw) {
    __shared__ float tile[32][33];
    int e = blockIdx.z;
    int isUp = blockIdx.x >= 32;
    int n0 = (blockIdx.x & 31) * 64;   // wait: 2048/32 = 64 tiles... see below
    // Re-derive: N=2048 needs 64 n-tiles of 32; grid.x = 128 (64 gate + 64 up)
    isUp = blockIdx.x >= 64;
    n0 = (blockIdx.x & 63) * 32;
    int k0 = blockIdx.y * 32;
    const float* s = (isUp ? uw : gw) + (size_t)e * H_DIM * I_DIM;
    int tx = threadIdx.x, ty = threadIdx.y;   // 32 x 8
#pragma unroll
    for (int i = 0; i < 32; i += 8)
        tile[ty + i][tx] = s[(size_t)(k0 + ty + i) * I_DIM + n0 + tx];
    __syncthreads();
#pragma unroll
    for (int i = 0; i < 32; i += 8) {
        float v = tf32_rna(tile[tx][ty + i]);
        size_t row = (size_t)e * 4096 + (size_t)(n0 + ty + i) * 2 + isUp;
        g_B1[row * H_DIM + k0 + tx] = v;
    }
}

// ---------------------------------------------------------------------------
// 4b) W2 conversion: fp32 [e][K=2048][N=1024] -> tf32(rna) K-major.
// ---------------------------------------------------------------------------
__global__ void conv_w2_kernel(const float* __restrict__ ow) {
    __shared__ float tile[32][33];
    int e = blockIdx.z;
    int k0 = blockIdx.y * 32, n0 = blockIdx.x * 32;
    const float* s = ow + (size_t)e * I_DIM * H_DIM;
    int tx = threadIdx.x, ty = threadIdx.y;
#pragma unroll
    for (int i = 0; i < 32; i += 8)
        tile[ty + i][tx] = s[(size_t)(k0 + ty + i) * H_DIM + n0 + tx];
    __syncthreads();
#pragma unroll
    for (int i = 0; i < 32; i += 8) {
        float v = tf32_rna(tile[tx][ty + i]);
        size_t row = (size_t)e * H_DIM + (size_t)(n0 + ty + i);
        g_W2[row * I_DIM + k0 + tx] = v;
    }
}

// ---------------------------------------------------------------------------
// 5) gather + round activations
// ---------------------------------------------------------------------------
__global__ void convA_kernel(const float* __restrict__ x) {
    int r = blockIdx.x;
    int c = threadIdx.x * 4;
    int token = g_row_token[r];
    float4 v = *(const float4*)(x + (size_t)token * H_DIM + c);
    v.x = tf32_rna(v.x); v.y = tf32_rna(v.y);
    v.z = tf32_rna(v.z); v.w = tf32_rna(v.w);
    *(float4*)(g_A1 + (size_t)r * H_DIM + c) = v;
}

// ---------------------------------------------------------------------------
// 6/7) Pipelined tf32 MMA grouped GEMM: D[128x128] = A[128xK] @ B[128xK]^T.
//   m16n8k8 single-product tf32, ldmatrix.b16 fragments (validated R15).
//   2-stage cp.async, k-chunk = 32 floats, __launch_bounds__(256, 2):
//   OCCUPANCY EXPERIMENT — 2 CTAs/SM (4 warps/SMSP) to test whether the
//   measured 12.5 cyc/MMA/SMSP is latency-bound (should drop toward ~8)
//   or legacy-pipe-bound (neutral).
//   Dynamic smem = 2 * 2 * 128 * 144 = 73728 B per CTA.
//   SRC=0: A=g_A1, B=g_B1, FUSE epilogue -> g_H = rna(silu(g)*u)
//   SRC=1: A=g_H,  B=g_W2, weighted epilogue -> g_partial
// ---------------------------------------------------------------------------
#define NST 2
#define ROW_P 144                // bytes per row (128B data + 16B pad; 9x16B)
#define TILE_B (128 * ROW_P)     // 18432
#define STAGE_B (2 * TILE_B)     // 36864
#define SMEM_SZ (NST * STAGE_B)  // 73728

template <int KCHUNKS, int ASTR, int BSTR, int BEROWS, bool FUSE, int SRC>
__global__ void __launch_bounds__(256, 2) mma_gemm() {
    const float* __restrict__ Ap = (SRC == 0) ? g_A1 : g_H;
    const float* __restrict__ Bp = (SRC == 0) ? g_B1 : g_W2;

    extern __shared__ char smem[];
    int e = blockIdx.z;
    int rowBeg = g_offs[e] + blockIdx.y * 128;
    int rowEnd = g_offs[e + 1];
    if (rowBeg >= rowEnd) return;
    int bx = blockIdx.x;
    int bRowBase = e * BEROWS + bx * 128;

    const int tid = threadIdx.x;
    const int wid = tid >> 5, lane = tid & 31;
    const int wm = wid >> 2, wn = wid & 3;
    uint32_t sb = smem_to_u32(smem);

    // ---- cp.async per-thread descriptors: 8 x 16B per stage ----
    const float* gptr[8];
    uint32_t dOff[8];
    uint32_t gsz[8];
#pragma unroll
    for (int j = 0; j < 8; j++) {
        int id  = j * 256 + tid;
        int arr = id >> 10;
        int q   = id & 1023;
        int row = q >> 3;
        int c16 = q & 7;
        dOff[j] = arr * TILE_B + row * ROW_P + c16 * 16;
        if (arr == 0) {
            int grow = rowBeg + row;
            bool ok = grow < rowEnd;
            int cr = ok ? grow : rowBeg;
            gptr[j] = Ap + (size_t)cr * ASTR + c16 * 4;
            gsz[j] = ok ? 16u : 0u;
        } else {
            gptr[j] = Bp + (size_t)(bRowBase + row) * BSTR + c16 * 4;
            gsz[j] = 16u;
        }
    }

    // ---- ldmatrix per-thread base offsets (validated R15 formulas) ----
    int mat = lane >> 3, mrow = lane & 7;
    uint32_t aBase[4], bBase[2];
    {
        int rA  = wm * 64 + (mat & 1) * 8 + mrow;
        int kAb = (mat >> 1) * 16;
#pragma unroll
        for (int mt = 0; mt < 4; mt++) aBase[mt] = (rA + mt * 16) * ROW_P + kAb;
        int rB  = wn * 32 + ((mat >> 1) & 1) * 8 + mrow;
        int kBb = (mat & 1) * 16;
#pragma unroll
        for (int nt = 0; nt < 2; nt++) bBase[nt] = (rB + nt * 16) * ROW_P + kBb;
    }

    float d[4][4][4];
#pragma unroll
    for (int i = 0; i < 4; i++)
#pragma unroll
        for (int j = 0; j < 4; j++)
#pragma unroll
            for (int c = 0; c < 4; c++) d[i][j][c] = 0.f;

    auto load_stage = [&](int s, int chunk) {
        uint32_t kByte = (uint32_t)chunk * 128;  // 32 floats
        uint32_t base = sb + s * STAGE_B;
#pragma unroll
        for (int j = 0; j < 8; j++)
            cp_async16(base + dOff[j], (const char*)gptr[j] + kByte, gsz[j]);
    };

    // prologue: stage 0 <- chunk 0
    load_stage(0, 0);
    cp_commit();

    for (int c = 0; c < KCHUNKS; c++) {
        cp_wait<0>();            // drain: only chunk c pending here
        __syncthreads();

        if (c + 1 < KCHUNKS) load_stage((c + 1) & 1, c + 1);
        cp_commit();

        uint32_t stA = sb + (c & 1) * STAGE_B;
        uint32_t stB = stA + TILE_B;
#pragma unroll
        for (int s = 0; s < 4; s++) {            // 4 k8 steps per 32-float chunk
            uint32_t kadd = s * 32;              // 8 floats
            uint32_t a[4][4], b[2][4];
#pragma unroll
            for (int mt = 0; mt < 4; mt++)
                LDSM4(a[mt], stA + aBase[mt] + kadd);
#pragma unroll
            for (int nt = 0; nt < 2; nt++)
                LDSM4(b[nt], stB + bBase[nt] + kadd);
#pragma unroll
            for (int mt = 0; mt < 4; mt++) {
#pragma unroll
                for (int n8 = 0; n8 < 4; n8++) {
                    int nt = n8 >> 1, g = (n8 & 1) * 2;
                    MMATF32(d[mt][n8], a[mt], b[nt][g], b[nt][g + 1]);
                }
            }
        }
        __syncthreads();   // stage c&1 fully consumed before overwrite next iter
    }

    // ---- epilogue (validated R15) ----
    if (FUSE) {
        float* sh = (float*)smem;                // [128][72] floats
        int g4 = lane >> 2, t4 = lane & 3;
#pragma unroll
        for (int mt = 0; mt < 4; mt++) {
#pragma unroll
            for (int n8 = 0; n8 < 4; n8++) {
                int r0 = wm * 64 + mt * 16 + g4;
                int i0 = wn * 16 + n8 * 4 + t4;
                float g0 = d[mt][n8][0], u0 = d[mt][n8][1];
                sh[r0 * 72 + i0] = tf32_rna((g0 / (1.0f + expf(-g0))) * u0);
                float g1 = d[mt][n8][2], u1 = d[mt][n8][3];
                sh[(r0 + 8) * 72 + i0] = tf32_rna((g1 / (1.0f + expf(-g1))) * u1);
            }
        }
        __syncthreads();
        int iBase = bx * 64;
#pragma unroll
        for (int j = 0; j < 8; j++) {
            int id = j * 256 + tid;          // 0..2047 = 128 rows x 16 chunks16B
            int row = id >> 4;
            int cc = id & 15;
            int grow = rowBeg + row;
            if (grow < rowEnd) {
                const char* s = smem + row * 288 + cc * 16;
                float* dptr = g_H + (size_t)grow * I_DIM + iBase + cc * 4;
                *(uint4*)dptr = *(const uint4*)s;
            }
        }
    } else {
        int g4 = lane >> 2, t4 = lane & 3;
#pragma unroll
        for (int mt = 0; mt < 4; mt++) {
#pragma unroll
            for (int n8 = 0; n8 < 4; n8++) {
                int r0 = rowBeg + wm * 64 + mt * 16 + g4;
                int col = bx * 128 + wn * 32 + n8 * 8 + t4 * 2;
                if (r0 < rowEnd) {
                    float w = g_row_weight[r0];
                    float2 v = make_float2(w * d[mt][n8][0], w * d[mt][n8][1]);
                    *(float2*)&g_partial[(size_t)r0 * H_DIM + col] = v;
                }
                int r1 = r0 + 8;
                if (r1 < rowEnd) {
                    float w = g_row_weight[r1];
                    float2 v = make_float2(w * d[mt][n8][2], w * d[mt][n8][3]);
                    *(float2*)&g_partial[(size_t)r1 * H_DIM + col] = v;
                }
            }
        }
    }
}

// ---------------------------------------------------------------------------
// 8) combine
// ---------------------------------------------------------------------------
__global__ void combine_kernel(float* __restrict__ out) {
    int idx = blockIdx.x * 256 + threadIdx.x;
    if (idx >= T_DIM * (H_DIM / 4)) return;
    int t = idx >> 8;
    int j = (idx & 255) * 4;
    int r0 = g_row_of_pair[2 * t];
    int r1 = g_row_of_pair[2 * t + 1];
    float4 a = *(float4*)&g_partial[(size_t)r0 * H_DIM + j];
    float4 b = *(float4*)&g_partial[(size_t)r1 * H_DIM + j];
    float4 o;
    o.x = a.x + b.x; o.y = a.y + b.y; o.z = a.z + b.z; o.w = a.w + b.w;
    *(float4*)(out + (size_t)t * H_DIM + j) = o;
}

// ---------------------------------------------------------------------------
// launch
// ---------------------------------------------------------------------------
extern "C" void kernel_launch(void* const* d_in, const int* in_sizes, int n_in,
                              void* d_out, int out_size) {
    const float* x  = (const float*)d_in[0];
    const float* rw = (const float*)d_in[1];
    const float* gw = (const float*)d_in[2];
    const float* uw = (const float*)d_in[3];
    const float* ow = (const float*)d_in[4];
    float* out = (float*)d_out;

    int write_logits = (out_size >= T_DIM * H_DIM + T_DIM * E_DIM) ? 1 : 0;
    float* logits = out + (size_t)T_DIM * H_DIM;

    cudaFuncSetAttribute(mma_gemm<32, 1024, 1024, 4096, true, 0>,
                         cudaFuncAttributeMaxDynamicSharedMemorySize, SMEM_SZ);
    cudaFuncSetAttribute(mma_gemm<64, 2048, 2048, 1024, false, 1>,
                         cudaFuncAttributeMaxDynamicSharedMemorySize, SMEM_SZ);

    init_kernel<<<1, 32>>>();
    router_kernel<<<T_DIM / 8, 256>>>(x, rw, logits, write_logits);
    offsets_kernel<<<1, 32>>>();
    scatter_kernel<<<NPAIR / 256, 256>>>();

    // weight conversion (transpose + tf32 rna)
    dim3 cb(32, 8);
    conv_b1_kernel<<<dim3(128, H_DIM / 32, E_DIM), cb>>>(gw, uw);
    conv_w2_kernel<<<dim3(H_DIM / 32, I_DIM / 32, E_DIM), cb>>>(ow);
    convA_kernel<<<NPAIR, 256>>>(x);

    // pipelined tf32 grouped GEMMs (72KB smem, 2 CTAs/SM occupancy experiment)
    mma_gemm<32, 1024, 1024, 4096, true, 0><<<dim3(32, 32, E_DIM), 256, SMEM_SZ>>>();
    mma_gemm<64, 2048, 2048, 1024, false, 1><<<dim3(8, 32, E_DIM), 256, SMEM_SZ>>>();

    combine_kernel<<<(T_DIM * (H_DIM / 4) + 255) / 256, 256>>>(out);
}

// round 17
// speedup vs baseline: 3.6771x; 1.0044x over previous
#include <cuda_runtime.h>
#include <cuda_bf16.h>
#include <cstdint>
#include <math.h>

// Problem constants
#define T_DIM 4096
#define H_DIM 1024
#define I_DIM 2048
#define E_DIM 8
#define NPAIR (T_DIM * 2)   // 8192

// ---------------------------------------------------------------------------
// Static device scratch (no allocations allowed).
// Referenced ONLY from device code (host-passing these was the R7-R11 bug).
// All tf32 values stored as fp32 bit patterns (low 13 mantissa bits zero).
// ---------------------------------------------------------------------------
__device__ float g_B1[(size_t)E_DIM * 4096 * H_DIM];   // interleaved rows: 2i=gate_i, 2i+1=up_i; K-major
__device__ float g_W2[(size_t)E_DIM * H_DIM * I_DIM];  // [e][n=1024][k=2048]
__device__ float g_A1[(size_t)NPAIR * H_DIM];
__device__ float g_H [(size_t)NPAIR * I_DIM];
__device__ float g_partial[(size_t)NPAIR * H_DIM];
__device__ int   g_count[E_DIM];
__device__ int   g_cursor[E_DIM];
__device__ int   g_offs[E_DIM + 1];
__device__ int   g_expert_sel[NPAIR];
__device__ float g_pair_w[NPAIR];
__device__ int   g_row_token[NPAIR];
__device__ float g_row_weight[NPAIR];
__device__ int   g_row_of_pair[NPAIR];

// ---------------------------------------------------------------------------
// PTX helpers (arch-portable: cp.async / ldmatrix / mma.sync tf32)
// ---------------------------------------------------------------------------
__device__ __forceinline__ uint32_t smem_to_u32(const void* p) {
    uint32_t a;
    asm("{ .reg .u64 t; cvta.to.shared.u64 t, %1; cvt.u32.u64 %0, t; }" : "=r"(a) : "l"(p));
    return a;
}
__device__ __forceinline__ void cp_async16(uint32_t dst, const void* src, uint32_t srcBytes) {
    asm volatile("cp.async.cg.shared.global [%0], [%1], 16, %2;"
                 :: "r"(dst), "l"(src), "r"(srcBytes) : "memory");
}
__device__ __forceinline__ void cp_commit() {
    asm volatile("cp.async.commit_group;" ::: "memory");
}
template <int N>
__device__ __forceinline__ void cp_wait() {
    asm volatile("cp.async.wait_group %0;" :: "n"(N) : "memory");
}
__device__ __forceinline__ float tf32_rna(float v) {
    uint32_t o;
    asm("cvt.rna.tf32.f32 %0, %1;" : "=r"(o) : "f"(v));
    return __uint_as_float(o);
}

#define LDSM4(r, addr) \
    asm volatile("ldmatrix.sync.aligned.m8n8.x4.shared.b16 {%0,%1,%2,%3}, [%4];" \
                 : "=r"((r)[0]), "=r"((r)[1]), "=r"((r)[2]), "=r"((r)[3]) : "r"(addr))

#define MMATF32(d, a, b0, b1) \
    asm volatile("mma.sync.aligned.m16n8k8.row.col.f32.tf32.tf32.f32 " \
                 "{%0,%1,%2,%3}, {%4,%5,%6,%7}, {%8,%9}, {%0,%1,%2,%3};" \
                 : "+f"((d)[0]), "+f"((d)[1]), "+f"((d)[2]), "+f"((d)[3]) \
                 : "r"((a)[0]), "r"((a)[1]), "r"((a)[2]), "r"((a)[3]), "r"(b0), "r"(b1))

// ---------------------------------------------------------------------------
// 0) init
// ---------------------------------------------------------------------------
__global__ void init_kernel() {
    int i = threadIdx.x;
    if (i < E_DIM) { g_count[i] = 0; g_cursor[i] = 0; }
}

// ---------------------------------------------------------------------------
// 1) router (fp32 exact)
// ---------------------------------------------------------------------------
__global__ void router_kernel(const float* __restrict__ x,
                              const float* __restrict__ rw,
                              float* __restrict__ logits_out,
                              int write_logits) {
    int t = blockIdx.x * 8 + (threadIdx.x >> 5);
    if (t >= T_DIM) return;
    int lane = threadIdx.x & 31;
    float acc[E_DIM];
#pragma unroll
    for (int e = 0; e < E_DIM; e++) acc[e] = 0.f;
    const float* xp = x + (size_t)t * H_DIM;
    for (int h = lane; h < H_DIM; h += 32) {
        float xv = xp[h];
        const float* r = rw + (size_t)h * E_DIM;
#pragma unroll
        for (int e = 0; e < E_DIM; e++) acc[e] += xv * r[e];
    }
#pragma unroll
    for (int e = 0; e < E_DIM; e++) {
#pragma unroll
        for (int off = 16; off; off >>= 1)
            acc[e] += __shfl_xor_sync(0xffffffffu, acc[e], off);
    }
    if (lane == 0) {
        if (write_logits) {
#pragma unroll
            for (int e = 0; e < E_DIM; e++) logits_out[(size_t)t * E_DIM + e] = acc[e];
        }
        int e0 = 0;
#pragma unroll
        for (int e = 1; e < E_DIM; e++) if (acc[e] > acc[e0]) e0 = e;
        int e1 = (e0 == 0) ? 1 : 0;
#pragma unroll
        for (int e = 0; e < E_DIM; e++)
            if (e != e0 && acc[e] > acc[e1]) e1 = e;
        float r1 = expf(acc[e1] - acc[e0]);
        float s  = 1.0f + r1;
        g_expert_sel[t * 2 + 0] = e0;
        g_expert_sel[t * 2 + 1] = e1;
        g_pair_w[t * 2 + 0] = 1.0f / s;
        g_pair_w[t * 2 + 1] = r1 / s;
        atomicAdd(&g_count[e0], 1);
        atomicAdd(&g_count[e1], 1);
    }
}

// ---------------------------------------------------------------------------
// 2) offsets  3) scatter
// ---------------------------------------------------------------------------
__global__ void offsets_kernel() {
    if (threadIdx.x == 0) {
        int acc = 0;
        g_offs[0] = 0;
#pragma unroll
        for (int e = 0; e < E_DIM; e++) { acc += g_count[e]; g_offs[e + 1] = acc; }
    }
}

__global__ void scatter_kernel() {
    int p = blockIdx.x * 256 + threadIdx.x;
    if (p >= NPAIR) return;
    int e = g_expert_sel[p];
    int r = g_offs[e] + atomicAdd(&g_cursor[e], 1);
    g_row_token[r]  = p >> 1;
    g_row_weight[r] = g_pair_w[p];
    g_row_of_pair[p] = r;
}

// ---------------------------------------------------------------------------
// 4a) B1 conversion (gate+up merged): fp32 [e][K=1024][N=2048] -> tf32(rna),
//     K-major interleaved rows (2n = gate_n, 2n+1 = up_n).
//     grid.x = 128: 0..63 -> gate, 64..127 -> up.
// ---------------------------------------------------------------------------
__global__ void conv_b1_kernel(const float* __restrict__ gw,
                               const float* __restrict__ uw) {
    __shared__ float tile[32][33];
    int e = blockIdx.z;
    int isUp = blockIdx.x >= 64;
    int n0 = (blockIdx.x & 63) * 32;
    int k0 = blockIdx.y * 32;
    const float* s = (isUp ? uw : gw) + (size_t)e * H_DIM * I_DIM;
    int tx = threadIdx.x, ty = threadIdx.y;   // 32 x 8
#pragma unroll
    for (int i = 0; i < 32; i += 8)
        tile[ty + i][tx] = s[(size_t)(k0 + ty + i) * I_DIM + n0 + tx];
    __syncthreads();
#pragma unroll
    for (int i = 0; i < 32; i += 8) {
        float v = tf32_rna(tile[tx][ty + i]);
        size_t row = (size_t)e * 4096 + (size_t)(n0 + ty + i) * 2 + isUp;
        g_B1[row * H_DIM + k0 + tx] = v;
    }
}

// ---------------------------------------------------------------------------
// 4b) W2 conversion: fp32 [e][K=2048][N=1024] -> tf32(rna) K-major.
// ---------------------------------------------------------------------------
__global__ void conv_w2_kernel(const float* __restrict__ ow) {
    __shared__ float tile[32][33];
    int e = blockIdx.z;
    int k0 = blockIdx.y * 32, n0 = blockIdx.x * 32;
    const float* s = ow + (size_t)e * I_DIM * H_DIM;
    int tx = threadIdx.x, ty = threadIdx.y;
#pragma unroll
    for (int i = 0; i < 32; i += 8)
        tile[ty + i][tx] = s[(size_t)(k0 + ty + i) * H_DIM + n0 + tx];
    __syncthreads();
#pragma unroll
    for (int i = 0; i < 32; i += 8) {
        float v = tf32_rna(tile[tx][ty + i]);
        size_t row = (size_t)e * H_DIM + (size_t)(n0 + ty + i);
        g_W2[row * I_DIM + k0 + tx] = v;
    }
}

// ---------------------------------------------------------------------------
// 5) gather + round activations
// ---------------------------------------------------------------------------
__global__ void convA_kernel(const float* __restrict__ x) {
    int r = blockIdx.x;
    int c = threadIdx.x * 4;
    int token = g_row_token[r];
    float4 v = *(const float4*)(x + (size_t)token * H_DIM + c);
    v.x = tf32_rna(v.x); v.y = tf32_rna(v.y);
    v.z = tf32_rna(v.z); v.w = tf32_rna(v.w);
    *(float4*)(g_A1 + (size_t)r * H_DIM + c) = v;
}

// ---------------------------------------------------------------------------
// 6/7) Pipelined tf32 MMA grouped GEMM: D[128x128] = A[128xK] @ B[128xK]^T.
//   m16n8k8 single-product tf32, ldmatrix.b16 fragments (validated R15/R16).
//   3-stage cp.async pipeline, k-chunk = 32 floats, 2 CTAs/SM:
//   smem 3*36864 = 110592 B/CTA, 2 CTAs = 221184 B/SM (fits 228KB budget).
//   cp.async.wait_group 1 -> chunk c was issued one full iteration ago,
//   closing the exposed-latency gap left by R16's 2-stage full drain.
//   SRC=0: A=g_A1, B=g_B1, FUSE epilogue -> g_H = rna(silu(g)*u)
//   SRC=1: A=g_H,  B=g_W2, weighted epilogue -> g_partial
// ---------------------------------------------------------------------------
#define NST 3
#define ROW_P 144                // bytes per row (128B data + 16B pad; 9x16B)
#define TILE_B (128 * ROW_P)     // 18432
#define STAGE_B (2 * TILE_B)     // 36864
#define SMEM_SZ (NST * STAGE_B)  // 110592

template <int KCHUNKS, int ASTR, int BSTR, int BEROWS, bool FUSE, int SRC>
__global__ void __launch_bounds__(256, 2) mma_gemm() {
    const float* __restrict__ Ap = (SRC == 0) ? g_A1 : g_H;
    const float* __restrict__ Bp = (SRC == 0) ? g_B1 : g_W2;

    extern __shared__ char smem[];
    int e = blockIdx.z;
    int rowBeg = g_offs[e] + blockIdx.y * 128;
    int rowEnd = g_offs[e + 1];
    if (rowBeg >= rowEnd) return;
    int bx = blockIdx.x;
    int bRowBase = e * BEROWS + bx * 128;

    const int tid = threadIdx.x;
    const int wid = tid >> 5, lane = tid & 31;
    const int wm = wid >> 2, wn = wid & 3;
    uint32_t sb = smem_to_u32(smem);

    // ---- cp.async per-thread descriptors: 8 x 16B per stage ----
    const float* gptr[8];
    uint32_t dOff[8];
    uint32_t gsz[8];
#pragma unroll
    for (int j = 0; j < 8; j++) {
        int id  = j * 256 + tid;
        int arr = id >> 10;
        int q   = id & 1023;
        int row = q >> 3;
        int c16 = q & 7;
        dOff[j] = arr * TILE_B + row * ROW_P + c16 * 16;
        if (arr == 0) {
            int grow = rowBeg + row;
            bool ok = grow < rowEnd;
            int cr = ok ? grow : rowBeg;
            gptr[j] = Ap + (size_t)cr * ASTR + c16 * 4;
            gsz[j] = ok ? 16u : 0u;
        } else {
            gptr[j] = Bp + (size_t)(bRowBase + row) * BSTR + c16 * 4;
            gsz[j] = 16u;
        }
    }

    // ---- ldmatrix per-thread base offsets (validated R15 formulas) ----
    int mat = lane >> 3, mrow = lane & 7;
    uint32_t aBase[4], bBase[2];
    {
        int rA  = wm * 64 + (mat & 1) * 8 + mrow;
        int kAb = (mat >> 1) * 16;
#pragma unroll
        for (int mt = 0; mt < 4; mt++) aBase[mt] = (rA + mt * 16) * ROW_P + kAb;
        int rB  = wn * 32 + ((mat >> 1) & 1) * 8 + mrow;
        int kBb = (mat & 1) * 16;
#pragma unroll
        for (int nt = 0; nt < 2; nt++) bBase[nt] = (rB + nt * 16) * ROW_P + kBb;
    }

    float d[4][4][4];
#pragma unroll
    for (int i = 0; i < 4; i++)
#pragma unroll
        for (int j = 0; j < 4; j++)
#pragma unroll
            for (int c = 0; c < 4; c++) d[i][j][c] = 0.f;

    auto load_stage = [&](int s, int chunk) {
        uint32_t kByte = (uint32_t)chunk * 128;  // 32 floats
        uint32_t base = sb + s * STAGE_B;
#pragma unroll
        for (int j = 0; j < 8; j++)
            cp_async16(base + dOff[j], (const char*)gptr[j] + kByte, gsz[j]);
    };

    // prologue: stages 0,1 <- chunks 0,1
    load_stage(0, 0);
    cp_commit();
    load_stage(1, 1);
    cp_commit();

    int stComp = 0;   // stage holding chunk c
    int stNext = 2;   // stage to fill with chunk c+2
    for (int c = 0; c < KCHUNKS; c++) {
        cp_wait<1>();            // chunk c complete (chunk c+1 may be in flight)
        __syncthreads();

        // fill stage stNext with chunk c+2; stNext was last READ in iter c-1.
        if (c + 2 < KCHUNKS) load_stage(stNext, c + 2);
        cp_commit();

        uint32_t stA = sb + stComp * STAGE_B;
        uint32_t stB = stA + TILE_B;
#pragma unroll
        for (int s = 0; s < 4; s++) {            // 4 k8 steps per 32-float chunk
            uint32_t kadd = s * 32;              // 8 floats
            uint32_t a[4][4], b[2][4];
#pragma unroll
            for (int mt = 0; mt < 4; mt++)
                LDSM4(a[mt], stA + aBase[mt] + kadd);
#pragma unroll
            for (int nt = 0; nt < 2; nt++)
                LDSM4(b[nt], stB + bBase[nt] + kadd);
#pragma unroll
            for (int mt = 0; mt < 4; mt++) {
#pragma unroll
                for (int n8 = 0; n8 < 4; n8++) {
                    int nt = n8 >> 1, g = (n8 & 1) * 2;
                    MMATF32(d[mt][n8], a[mt], b[nt][g], b[nt][g + 1]);
                }
            }
        }
        __syncthreads();   // stage stComp fully consumed before it is refilled

        stComp = (stComp == NST - 1) ? 0 : stComp + 1;
        stNext = (stNext == NST - 1) ? 0 : stNext + 1;
    }

    // ---- epilogue (validated R15/R16) ----
    if (FUSE) {
        float* sh = (float*)smem;                // [128][72] floats
        int g4 = lane >> 2, t4 = lane & 3;
#pragma unroll
        for (int mt = 0; mt < 4; mt++) {
#pragma unroll
            for (int n8 = 0; n8 < 4; n8++) {
                int r0 = wm * 64 + mt * 16 + g4;
                int i0 = wn * 16 + n8 * 4 + t4;
                float g0 = d[mt][n8][0], u0 = d[mt][n8][1];
                sh[r0 * 72 + i0] = tf32_rna((g0 / (1.0f + expf(-g0))) * u0);
                float g1 = d[mt][n8][2], u1 = d[mt][n8][3];
                sh[(r0 + 8) * 72 + i0] = tf32_rna((g1 / (1.0f + expf(-g1))) * u1);
            }
        }
        __syncthreads();
        int iBase = bx * 64;
#pragma unroll
        for (int j = 0; j < 8; j++) {
            int id = j * 256 + tid;          // 0..2047 = 128 rows x 16 chunks16B
            int row = id >> 4;
            int cc = id & 15;
            int grow = rowBeg + row;
            if (grow < rowEnd) {
                const char* s = smem + row * 288 + cc * 16;
                float* dptr = g_H + (size_t)grow * I_DIM + iBase + cc * 4;
                *(uint4*)dptr = *(const uint4*)s;
            }
        }
    } else {
        int g4 = lane >> 2, t4 = lane & 3;
#pragma unroll
        for (int mt = 0; mt < 4; mt++) {
#pragma unroll
            for (int n8 = 0; n8 < 4; n8++) {
                int r0 = rowBeg + wm * 64 + mt * 16 + g4;
                int col = bx * 128 + wn * 32 + n8 * 8 + t4 * 2;
                if (r0 < rowEnd) {
                    float w = g_row_weight[r0];
                    float2 v = make_float2(w * d[mt][n8][0], w * d[mt][n8][1]);
                    *(float2*)&g_partial[(size_t)r0 * H_DIM + col] = v;
                }
                int r1 = r0 + 8;
                if (r1 < rowEnd) {
                    float w = g_row_weight[r1];
                    float2 v = make_float2(w * d[mt][n8][2], w * d[mt][n8][3]);
                    *(float2*)&g_partial[(size_t)r1 * H_DIM + col] = v;
                }
            }
        }
    }
}

// ---------------------------------------------------------------------------
// 8) combine
// ---------------------------------------------------------------------------
__global__ void combine_kernel(float* __restrict__ out) {
    int idx = blockIdx.x * 256 + threadIdx.x;
    if (idx >= T_DIM * (H_DIM / 4)) return;
    int t = idx >> 8;
    int j = (idx & 255) * 4;
    int r0 = g_row_of_pair[2 * t];
    int r1 = g_row_of_pair[2 * t + 1];
    float4 a = *(float4*)&g_partial[(size_t)r0 * H_DIM + j];
    float4 b = *(float4*)&g_partial[(size_t)r1 * H_DIM + j];
    float4 o;
    o.x = a.x + b.x; o.y = a.y + b.y; o.z = a.z + b.z; o.w = a.w + b.w;
    *(float4*)(out + (size_t)t * H_DIM + j) = o;
}

// ---------------------------------------------------------------------------
// launch
// ---------------------------------------------------------------------------
extern "C" void kernel_launch(void* const* d_in, const int* in_sizes, int n_in,
                              void* d_out, int out_size) {
    const float* x  = (const float*)d_in[0];
    const float* rw = (const float*)d_in[1];
    const float* gw = (const float*)d_in[2];
    const float* uw = (const float*)d_in[3];
    const float* ow = (const float*)d_in[4];
    float* out = (float*)d_out;

    int write_logits = (out_size >= T_DIM * H_DIM + T_DIM * E_DIM) ? 1 : 0;
    float* logits = out + (size_t)T_DIM * H_DIM;

    cudaFuncSetAttribute(mma_gemm<32, 1024, 1024, 4096, true, 0>,
                         cudaFuncAttributeMaxDynamicSharedMemorySize, SMEM_SZ);
    cudaFuncSetAttribute(mma_gemm<64, 2048, 2048, 1024, false, 1>,
                         cudaFuncAttributeMaxDynamicSharedMemorySize, SMEM_SZ);

    init_kernel<<<1, 32>>>();
    router_kernel<<<T_DIM / 8, 256>>>(x, rw, logits, write_logits);
    offsets_kernel<<<1, 32>>>();
    scatter_kernel<<<NPAIR / 256, 256>>>();

    // weight conversion (transpose + tf32 rna)
    dim3 cb(32, 8);
    conv_b1_kernel<<<dim3(128, H_DIM / 32, E_DIM), cb>>>(gw, uw);
    conv_w2_kernel<<<dim3(H_DIM / 32, I_DIM / 32, E_DIM), cb>>>(ow);
    convA_kernel<<<NPAIR, 256>>>(x);

    // pipelined tf32 grouped GEMMs (3-stage, 110.6KB smem, 2 CTAs/SM)
    mma_gemm<32, 1024, 1024, 4096, true, 0><<<dim3(32, 32, E_DIM), 256, SMEM_SZ>>>();
    mma_gemm<64, 2048, 2048, 1024, false, 1><<<dim3(8, 32, E_DIM), 256, SMEM_SZ>>>();

    combine_kernel<<<(T_DIM * (H_DIM / 4) + 255) / 256, 256>>>(out);
}